// round 5
// baseline (speedup 1.0000x reference)
#include <cuda_runtime.h>
#include <cuda_fp16.h>

#define NO_MAX 100000
#define NR_MAX 1000
#define E_MAX  1000000

// ---------------- scratch (device globals; no allocations) ----------------
__device__ float g_A[NR_MAX * 64];      // Wk @ q_r
__device__ float g_c1[NR_MAX];          // q_r . bk
__device__ float g_qWe[NR_MAX * 4];     // We @ q_r
__device__ float g_rskip[NR_MAX * 64];  // x_rider@Wskip + bskip
__device__ float g_Wc[64 * 128];        // Wp @ W1[0:64]
__device__ float g_cvec[128];           // omega@W1c + b1 + bp@W1a
__device__ int   g_counts[NR_MAX];
__device__ int   g_starts[NR_MAX];
__device__ int   g_cursor[NR_MAX];
__device__ __align__(16) int    g_so[E_MAX];     // sorted order idx
__device__ __align__(16) int    g_pe[E_MAX];     // sorted original edge id
__device__ __align__(16) float4 g_sea[E_MAX];    // sorted edge_attr
__device__ __align__(16) __half g_Oh[(long long)NO_MAX * 128];  // 25.6 MB fp16
__device__ __align__(16) __half g_xoh[(long long)NO_MAX * 64];  // 12.8 MB fp16 x_order

// packed fp32x2 FMA (sm_100+): two independent fp32 FMAs per instruction
__device__ __forceinline__ unsigned long long fma2(unsigned long long a,
                                                   unsigned long long b,
                                                   unsigned long long c) {
    unsigned long long d;
    asm("fma.rn.f32x2 %0, %1, %2, %3;" : "=l"(d) : "l"(a), "l"(b), "l"(c));
    return d;
}
__device__ __forceinline__ unsigned long long pack2(float x) {
    unsigned long long d;
    asm("mov.b64 %0, {%1, %1};" : "=l"(d) : "r"(__float_as_uint(x)));
    return d;
}
__device__ __forceinline__ float2 unpack2(unsigned long long v) {
    unsigned lo, hi;
    asm("mov.b64 {%0, %1}, %2;" : "=r"(lo), "=r"(hi) : "l"(v));
    return make_float2(__uint_as_float(lo), __uint_as_float(hi));
}

// ---------------- fused prologue: rider precompute + const + Wc + zero ----------------
__global__ void __launch_bounds__(128) k_pre(
    const float* __restrict__ xr,
    const float* __restrict__ Wq, const float* __restrict__ bq,
    const float* __restrict__ Wk, const float* __restrict__ bk,
    const float* __restrict__ We,
    const float* __restrict__ Wsk, const float* __restrict__ bsk,
    const float* __restrict__ omg, const float* __restrict__ W1,
    const float* __restrict__ b1, const float* __restrict__ bp,
    const float* __restrict__ Wp, int NRv) {
    int b = blockIdx.x, h = threadIdx.x;
    if (b < NRv) {
        int r = b;
        __shared__ float xs[32], qs[64];
        if (h < 32) xs[h] = xr[r * 32 + h];
        __syncthreads();
        if (h < 64) {
            float q = bq[h];
#pragma unroll 8
            for (int d = 0; d < 32; d++) q += xs[d] * Wq[d * 64 + h];
            qs[h] = q;
            float sk = bsk[h];
#pragma unroll 8
            for (int d = 0; d < 32; d++) sk += xs[d] * Wsk[d * 64 + h];
            g_rskip[r * 64 + h] = sk;
        }
        __syncthreads();
        if (h < 64) {
            float a = 0.f;
#pragma unroll 8
            for (int t = 0; t < 64; t++) a += Wk[h * 64 + t] * qs[t];
            g_A[r * 64 + h] = a;
        }
        if (h < 4) {
            float w = 0.f;
            for (int t = 0; t < 64; t++) w += We[h * 64 + t] * qs[t];
            g_qWe[r * 4 + h] = w;
        }
        if (h == 0) {
            float c = 0.f;
            for (int t = 0; t < 64; t++) c += bk[t] * qs[t];
            g_c1[r] = c;
        }
    } else if (b == NRv) {
        // cvec
        float c = b1[h];
        for (int m = 0; m < 32; m++) c += omg[m] * W1[(128 + m) * 128 + h];
        for (int d = 0; d < 64; d++) c += bp[d] * W1[d * 128 + h];
        g_cvec[h] = c;
    } else if (b < NRv + 65) {
        // Wc row d
        int d = b - NRv - 1;
        __shared__ float wp[64];
        if (h < 64) wp[h] = Wp[d * 64 + h];
        __syncthreads();
        float acc = 0.f;
#pragma unroll 8
        for (int t = 0; t < 64; t++) acc += wp[t] * W1[t * 128 + h];
        g_Wc[d * 128 + h] = acc;
    } else {
        for (int i = h; i < NRv; i += 128) g_counts[i] = 0;
    }
}

// ---------------- bucket edges by rider (counting sort) ----------------
__global__ void k_hist(const int* __restrict__ ridx, int E, int NRv) {
    __shared__ int sh[NR_MAX];
    int tid = threadIdx.x;
    for (int i = tid; i < NRv; i += blockDim.x) sh[i] = 0;
    __syncthreads();
    for (int e = blockIdx.x * blockDim.x + tid; e < E; e += gridDim.x * blockDim.x)
        atomicAdd(&sh[ridx[e]], 1);
    __syncthreads();
    for (int i = tid; i < NRv; i += blockDim.x) {
        int c = sh[i];
        if (c) atomicAdd(&g_counts[i], c);
    }
}

__global__ void k_scan(int NRv) {
    __shared__ int s[1024];
    int t = threadIdx.x;
    int v = (t < NRv) ? g_counts[t] : 0;
    s[t] = v;
    __syncthreads();
    for (int off = 1; off < 1024; off <<= 1) {
        int u = (t >= off) ? s[t - off] : 0;
        __syncthreads();
        s[t] += u;
        __syncthreads();
    }
    if (t < NRv) {
        int st = s[t] - v;
        g_starts[t] = st;
        g_cursor[t] = st;
    }
}

__global__ void k_scatter(const int* __restrict__ ridx, const int* __restrict__ oidx,
                          const float* __restrict__ eat, int E) {
    for (int e = blockIdx.x * blockDim.x + threadIdx.x; e < E; e += gridDim.x * blockDim.x) {
        int r = ridx[e];
        int pos = atomicAdd(&g_cursor[r], 1);
        g_so[pos] = oidx[e];
        g_pe[pos] = e;
        g_sea[pos] = ((const float4*)eat)[e];
    }
}

// ---------------- O = x_order @ Wc -> fp16; also pack x_order -> fp16 ----------------
__global__ void __launch_bounds__(256) k_O(const float* __restrict__ xo, int NOv) {
    extern __shared__ __align__(16) float dsm[];
    float* Xs  = dsm;             // [128][68]
    float* Wcs = dsm + 128 * 68;  // [64][128]
    int tx = threadIdx.x, ty = threadIdx.y;  // 16x16
    int tid = ty * 16 + tx;
    int row0 = blockIdx.x * 128;
    for (int i = tid; i < 64 * 32; i += 256)
        ((float4*)Wcs)[i] = ((const float4*)g_Wc)[i];
    for (int i = tid; i < 128 * 16; i += 256) {
        int row = i >> 4, kq = i & 15;
        float4 xv = make_float4(0.f, 0.f, 0.f, 0.f);
        int gr = row0 + row;
        if (gr < NOv) xv = ((const float4*)xo)[gr * 16 + kq];
        *((float4*)(Xs + row * 68 + kq * 4)) = xv;
    }
    __syncthreads();
    // emit fp16 copy of x_order
    for (int i = tid; i < 128 * 32; i += 256) {
        int row = i >> 5, c = i & 31;
        int gr = row0 + row;
        if (gr < NOv) {
            float a = Xs[row * 68 + 2 * c], b = Xs[row * 68 + 2 * c + 1];
            ((half2*)g_xoh)[(long long)gr * 32 + c] = __floats2half2_rn(a, b);
        }
    }
    unsigned long long acc2[8][4];
#pragma unroll
    for (int i = 0; i < 8; i++)
#pragma unroll
        for (int j = 0; j < 4; j++) acc2[i][j] = 0ull;
#pragma unroll 8
    for (int k = 0; k < 64; k++) {
        unsigned long long ab[8];
#pragma unroll
        for (int i = 0; i < 8; i++) ab[i] = pack2(Xs[(ty * 8 + i) * 68 + k]);
        const float* wrow = Wcs + k * 128;
        unsigned long long b0 = *(const unsigned long long*)(wrow + tx * 4);
        unsigned long long b1 = *(const unsigned long long*)(wrow + tx * 4 + 2);
        unsigned long long b2 = *(const unsigned long long*)(wrow + 64 + tx * 4);
        unsigned long long b3 = *(const unsigned long long*)(wrow + 64 + tx * 4 + 2);
#pragma unroll
        for (int i = 0; i < 8; i++) {
            acc2[i][0] = fma2(ab[i], b0, acc2[i][0]);
            acc2[i][1] = fma2(ab[i], b1, acc2[i][1]);
            acc2[i][2] = fma2(ab[i], b2, acc2[i][2]);
            acc2[i][3] = fma2(ab[i], b3, acc2[i][3]);
        }
    }
#pragma unroll
    for (int i = 0; i < 8; i++) {
        int gr = row0 + ty * 8 + i;
        if (gr < NOv) {
            half2* dst = (half2*)g_Oh + (long long)gr * 64;
            float2 p0 = unpack2(acc2[i][0]);
            float2 p1 = unpack2(acc2[i][1]);
            float2 p2 = unpack2(acc2[i][2]);
            float2 p3 = unpack2(acc2[i][3]);
            dst[tx * 2]          = __floats2half2_rn(p0.x, p0.y);
            dst[tx * 2 + 1]      = __floats2half2_rn(p1.x, p1.y);
            dst[32 + tx * 2]     = __floats2half2_rn(p2.x, p2.y);
            dst[32 + tx * 2 + 1] = __floats2half2_rn(p3.x, p3.y);
        }
    }
}

// ---------------- fused attention + edge scoring: one CTA per rider ----------------
__global__ void __launch_bounds__(256) k_fused(
    const float* __restrict__ Wv, const float* __restrict__ bv,
    const float* __restrict__ We, const float* __restrict__ Wp,
    const float* __restrict__ bp, const float* __restrict__ W1,
    const float* __restrict__ W2, const float* __restrict__ b2,
    float* __restrict__ out) {
    int r = blockIdx.x, tid = threadIdx.x;
    int lane = tid & 31, warp = tid >> 5;
    // NOTE: 16B alignment on every array accessed through float2/float4 casts
    __shared__ __align__(16) float As[64];
    __shared__ __align__(16) float qWes[4];
    __shared__ float c1s;
    __shared__ __align__(16) float wsum[8][64];
    __shared__ __align__(16) float wsc[8][8];
    __shared__ __align__(16) float xs_s[64];
    __shared__ __align__(16) float remb_s[64];
    __shared__ __align__(16) float eas[4];
    __shared__ float asum_s;
    __shared__ __align__(16) float Rcs[128];
    __shared__ __align__(16) float W2s[128];
    __shared__ __align__(16) float Wpre_s[64];
    __shared__ float c2s;
    if (tid < 64) As[tid] = g_A[r * 64 + tid];
    if (tid < 4)  qWes[tid] = g_qWe[r * 4 + tid];
    if (tid == 0) c1s = g_c1[r];
    if (tid < 128) W2s[tid] = W2[tid];
    __syncthreads();
    float2 a2 = ((const float2*)As)[lane];  // dims 2l, 2l+1
    float q0 = qWes[0], q1 = qWes[1], q2 = qWes[2], q3 = qWes[3], c1 = c1s;
    int start = g_starts[r], cnt = g_counts[r];

    // ---- phase 1: attention (fp16 x gathers) ----
    float xs0 = 0.f, xs1 = 0.f;
    float asum = 0.f, e0 = 0.f, e1 = 0.f, e2 = 0.f, e3 = 0.f;
    for (int i = warp; i < cnt; i += 8) {
        int idx = start + i;
        int o = __ldg(g_so + idx);           // broadcast
        float4 ea = __ldg(g_sea + idx);      // broadcast
        unsigned xu = __ldg((const unsigned*)g_xoh + (long long)o * 32 + lane);
        float2 xf = __half22float2(*(const half2*)&xu);
        float pd = xf.x * a2.x + xf.y * a2.y;
        pd += __shfl_xor_sync(0xffffffffu, pd, 16);
        pd += __shfl_xor_sync(0xffffffffu, pd, 8);
        pd += __shfl_xor_sync(0xffffffffu, pd, 4);
        pd += __shfl_xor_sync(0xffffffffu, pd, 2);
        pd += __shfl_xor_sync(0xffffffffu, pd, 1);
        float dot = pd + c1 + ea.x * q0 + ea.y * q1 + ea.z * q2 + ea.w * q3;
        float w = __expf(0.125f * dot);  // softmax shift-invariance: no max needed
        asum += w;
        e0 += w * ea.x; e1 += w * ea.y; e2 += w * ea.z; e3 += w * ea.w;
        xs0 += w * xf.x; xs1 += w * xf.y;
    }
    wsum[warp][2 * lane] = xs0;
    wsum[warp][2 * lane + 1] = xs1;
    if (lane == 0) {
        wsc[warp][0] = asum; wsc[warp][1] = e0; wsc[warp][2] = e1;
        wsc[warp][3] = e2;   wsc[warp][4] = e3;
    }
    __syncthreads();
    if (tid < 64) {
        float v = 0.f;
#pragma unroll
        for (int w = 0; w < 8; w++) v += wsum[w][tid];
        xs_s[tid] = v;
    }
    if (tid < 5) {
        float v = 0.f;
#pragma unroll
        for (int w = 0; w < 8; w++) v += wsc[w][tid];
        if (tid == 0) asum_s = v; else eas[tid - 1] = v;
    }
    __syncthreads();
    if (tid < 64) {
        int h = tid;
        float t = asum_s * bv[h];
#pragma unroll 8
        for (int d = 0; d < 64; d++) t += xs_s[d] * Wv[d * 64 + h];
        t += eas[0] * We[h] + eas[1] * We[64 + h] + eas[2] * We[128 + h] + eas[3] * We[192 + h];
        remb_s[h] = t / (asum_s + 1e-16f) + g_rskip[r * 64 + h];
    }
    __syncthreads();
    if (tid < 128) {
        float acc = g_cvec[tid];
#pragma unroll 8
        for (int h = 0; h < 64; h++) acc += remb_s[h] * W1[(64 + h) * 128 + tid];
        Rcs[tid] = acc;
    }
    if (tid < 64) {
        float acc = 0.f;
#pragma unroll 8
        for (int h = 0; h < 64; h++) acc += Wp[tid * 64 + h] * remb_s[h];
        Wpre_s[tid] = acc;
    }
    if (tid == 0) {
        float acc = 0.f;
        for (int h = 0; h < 64; h++) acc += bp[h] * remb_s[h];
        c2s = acc;
    }
    __syncthreads();

    // ---- phase 2: score this rider's edges ----
    float4 w4 = ((const float4*)W2s)[lane];   // hidden dims 4l..4l+3
    float4 rc4 = ((const float4*)Rcs)[lane];
    float2 p2 = ((const float2*)Wpre_s)[lane];  // dims 2l, 2l+1
    float tail = 0.125f * c2s + __ldg(b2);
    for (int i = warp; i < cnt; i += 8) {
        int idx = start + i;
        int o = __ldg(g_so + idx);
        int e = __ldg(g_pe + idx);
        uint2 Ou = __ldg((const uint2*)g_Oh + (long long)o * 32 + lane);
        unsigned xu = __ldg((const unsigned*)g_xoh + (long long)o * 32 + lane);
        float2 oA = __half22float2(*(const half2*)&Ou.x);
        float2 oB = __half22float2(*(const half2*)&Ou.y);
        float2 xf = __half22float2(*(const half2*)&xu);
        float part = 0.125f * (xf.x * p2.x + xf.y * p2.y);
        part += fmaxf(oA.x + rc4.x, 0.f) * w4.x;
        part += fmaxf(oA.y + rc4.y, 0.f) * w4.y;
        part += fmaxf(oB.x + rc4.z, 0.f) * w4.z;
        part += fmaxf(oB.y + rc4.w, 0.f) * w4.w;
        part += __shfl_xor_sync(0xffffffffu, part, 16);
        part += __shfl_xor_sync(0xffffffffu, part, 8);
        part += __shfl_xor_sync(0xffffffffu, part, 4);
        part += __shfl_xor_sync(0xffffffffu, part, 2);
        part += __shfl_xor_sync(0xffffffffu, part, 1);
        if (lane == 0) {
            float v = part + tail;
            out[e] = fminf(fmaxf(v, -10.f), 10.f);
        }
    }
}

// ---------------- launch ----------------
extern "C" void kernel_launch(void* const* d_in, const int* in_sizes, int n_in,
                              void* d_out, int out_size) {
    const float* xo   = (const float*)d_in[0];
    const float* xr   = (const float*)d_in[1];
    const float* eat  = (const float*)d_in[2];
    const int*   oidx = (const int*)d_in[3];
    const int*   ridx = (const int*)d_in[4];
    const float* omg  = (const float*)d_in[5];
    const float* Wk   = (const float*)d_in[6];
    const float* bk   = (const float*)d_in[7];
    const float* Wq   = (const float*)d_in[8];
    const float* bq   = (const float*)d_in[9];
    const float* Wv   = (const float*)d_in[10];
    const float* bv   = (const float*)d_in[11];
    const float* We   = (const float*)d_in[12];
    const float* Wsk  = (const float*)d_in[13];
    const float* bsk  = (const float*)d_in[14];
    const float* Wp   = (const float*)d_in[15];
    const float* bp   = (const float*)d_in[16];
    const float* W1   = (const float*)d_in[17];
    const float* b1   = (const float*)d_in[18];
    const float* W2   = (const float*)d_in[19];
    const float* b2   = (const float*)d_in[20];
    float* out = (float*)d_out;
    int NOv = in_sizes[0] / 64;
    int NRv = in_sizes[1] / 32;
    int E   = in_sizes[3];

    const int kO_smem = (128 * 68 + 64 * 128) * 4;  // 67584 B
    cudaFuncSetAttribute(k_O, cudaFuncAttributeMaxDynamicSharedMemorySize, kO_smem);

    k_pre<<<NRv + 66, 128>>>(xr, Wq, bq, Wk, bk, We, Wsk, bsk, omg, W1, b1, bp, Wp, NRv);
    k_hist<<<256, 256>>>(ridx, E, NRv);
    k_scan<<<1, 1024>>>(NRv);
    k_O<<<(NOv + 127) / 128, dim3(16, 16), kO_smem>>>(xo, NOv);
    k_scatter<<<512, 256>>>(ridx, oidx, eat, E);
    k_fused<<<NRv, 256>>>(Wv, bv, We, Wp, bp, W1, W2, b2, out);
}

// round 6
// speedup vs baseline: 1.0241x; 1.0241x over previous
#include <cuda_runtime.h>
#include <cuda_fp16.h>

#define NO_MAX 100000
#define NR_MAX 1000
#define E_MAX  1000000

struct __align__(16) Rec { int o; int e; int pad0; int pad1; float4 ea; };  // 32B = 1 sector

// ---------------- scratch (device globals; no allocations) ----------------
__device__ float g_A[NR_MAX * 64];      // Wk @ q_r
__device__ float g_c1[NR_MAX];          // q_r . bk
__device__ float g_qWe[NR_MAX * 4];     // We @ q_r
__device__ float g_rskip[NR_MAX * 64];  // x_rider@Wskip + bskip
__device__ float g_Wc[64 * 128];        // Wp @ W1[0:64]
__device__ float g_cvec[128];           // omega@W1c + b1 + bp@W1a
__device__ int   g_cnt_pad[NR_MAX * 32];    // padded: one counter per 128B sector
__device__ int   g_cursor_pad[NR_MAX * 32]; // padded
__device__ int   g_counts[NR_MAX];          // compact copy for k_fused
__device__ int   g_starts[NR_MAX];
__device__ __align__(16) Rec g_rec[E_MAX];  // 32 MB sorted records
__device__ __align__(16) __half g_Oh[(long long)NO_MAX * 128];  // 25.6 MB fp16
__device__ __align__(16) __half g_xoh[(long long)NO_MAX * 64];  // 12.8 MB fp16 x_order

// packed fp32x2 FMA (sm_100+)
__device__ __forceinline__ unsigned long long fma2(unsigned long long a,
                                                   unsigned long long b,
                                                   unsigned long long c) {
    unsigned long long d;
    asm("fma.rn.f32x2 %0, %1, %2, %3;" : "=l"(d) : "l"(a), "l"(b), "l"(c));
    return d;
}
__device__ __forceinline__ unsigned long long pack2(float x) {
    unsigned long long d;
    asm("mov.b64 %0, {%1, %1};" : "=l"(d) : "r"(__float_as_uint(x)));
    return d;
}
__device__ __forceinline__ float2 unpack2(unsigned long long v) {
    unsigned lo, hi;
    asm("mov.b64 {%0, %1}, %2;" : "=r"(lo), "=r"(hi) : "l"(v));
    return make_float2(__uint_as_float(lo), __uint_as_float(hi));
}

// ---------------- fused prologue: rider precompute + const + Wc + zero ----------------
__global__ void __launch_bounds__(128) k_pre(
    const float* __restrict__ xr,
    const float* __restrict__ Wq, const float* __restrict__ bq,
    const float* __restrict__ Wk, const float* __restrict__ bk,
    const float* __restrict__ We,
    const float* __restrict__ Wsk, const float* __restrict__ bsk,
    const float* __restrict__ omg, const float* __restrict__ W1,
    const float* __restrict__ b1, const float* __restrict__ bp,
    const float* __restrict__ Wp, int NRv) {
    int b = blockIdx.x, h = threadIdx.x;
    if (b < NRv) {
        int r = b;
        __shared__ float xs[32], qs[64];
        if (h < 32) xs[h] = xr[r * 32 + h];
        __syncthreads();
        if (h < 64) {
            float q = bq[h];
#pragma unroll 8
            for (int d = 0; d < 32; d++) q += xs[d] * Wq[d * 64 + h];
            qs[h] = q;
            float sk = bsk[h];
#pragma unroll 8
            for (int d = 0; d < 32; d++) sk += xs[d] * Wsk[d * 64 + h];
            g_rskip[r * 64 + h] = sk;
        }
        __syncthreads();
        if (h < 64) {
            float a = 0.f;
#pragma unroll 8
            for (int t = 0; t < 64; t++) a += Wk[h * 64 + t] * qs[t];
            g_A[r * 64 + h] = a;
        }
        if (h < 4) {
            float w = 0.f;
            for (int t = 0; t < 64; t++) w += We[h * 64 + t] * qs[t];
            g_qWe[r * 4 + h] = w;
        }
        if (h == 0) {
            float c = 0.f;
            for (int t = 0; t < 64; t++) c += bk[t] * qs[t];
            g_c1[r] = c;
        }
    } else if (b == NRv) {
        float c = b1[h];
        for (int m = 0; m < 32; m++) c += omg[m] * W1[(128 + m) * 128 + h];
        for (int d = 0; d < 64; d++) c += bp[d] * W1[d * 128 + h];
        g_cvec[h] = c;
    } else if (b < NRv + 65) {
        int d = b - NRv - 1;
        __shared__ float wp[64];
        if (h < 64) wp[h] = Wp[d * 64 + h];
        __syncthreads();
        float acc = 0.f;
#pragma unroll 8
        for (int t = 0; t < 64; t++) acc += wp[t] * W1[t * 128 + h];
        g_Wc[d * 128 + h] = acc;
    } else {
        for (int i = h; i < NRv; i += 128) g_cnt_pad[i * 32] = 0;
    }
}

// ---------------- bucket edges by rider (counting sort, padded atomics) ----------------
__global__ void k_hist(const int* __restrict__ ridx, int E, int NRv) {
    __shared__ int sh[NR_MAX];
    int tid = threadIdx.x;
    for (int i = tid; i < NRv; i += blockDim.x) sh[i] = 0;
    __syncthreads();
    for (int e = blockIdx.x * blockDim.x + tid; e < E; e += gridDim.x * blockDim.x)
        atomicAdd(&sh[ridx[e]], 1);
    __syncthreads();
    for (int i = tid; i < NRv; i += blockDim.x) {
        int c = sh[i];
        if (c) atomicAdd(&g_cnt_pad[i * 32], c);
    }
}

__global__ void k_scan(int NRv) {
    __shared__ int s[1024];
    int t = threadIdx.x;
    int v = (t < NRv) ? g_cnt_pad[t * 32] : 0;
    s[t] = v;
    __syncthreads();
    for (int off = 1; off < 1024; off <<= 1) {
        int u = (t >= off) ? s[t - off] : 0;
        __syncthreads();
        s[t] += u;
        __syncthreads();
    }
    if (t < NRv) {
        int st = s[t] - v;
        g_starts[t] = st;
        g_counts[t] = v;
        g_cursor_pad[t * 32] = st;
    }
}

__global__ void k_scatter(const int* __restrict__ ridx, const int* __restrict__ oidx,
                          const float* __restrict__ eat, int E) {
    for (int e = blockIdx.x * blockDim.x + threadIdx.x; e < E; e += gridDim.x * blockDim.x) {
        int r = ridx[e];
        int pos = atomicAdd(&g_cursor_pad[r * 32], 1);
        Rec* rp = &g_rec[pos];
        *(int4*)rp = make_int4(oidx[e], e, 0, 0);
        rp->ea = ((const float4*)eat)[e];
    }
}

// ---------------- O = x_order @ Wc -> fp16 (64-row tiles); pack x -> fp16 ----------------
__global__ void __launch_bounds__(256) k_O(const float* __restrict__ xo, int NOv) {
    extern __shared__ __align__(16) float dsm[];
    float* Xs  = dsm;            // [64][68]
    float* Wcs = dsm + 64 * 68;  // [64][128]
    int tx = threadIdx.x, ty = threadIdx.y;  // 16x16
    int tid = ty * 16 + tx;
    int row0 = blockIdx.x * 64;
    for (int i = tid; i < 64 * 32; i += 256)
        ((float4*)Wcs)[i] = ((const float4*)g_Wc)[i];
    for (int i = tid; i < 64 * 16; i += 256) {
        int row = i >> 4, kq = i & 15;
        float4 xv = make_float4(0.f, 0.f, 0.f, 0.f);
        int gr = row0 + row;
        if (gr < NOv) xv = ((const float4*)xo)[gr * 16 + kq];
        *((float4*)(Xs + row * 68 + kq * 4)) = xv;
    }
    __syncthreads();
    // emit fp16 copy of x_order
    for (int i = tid; i < 64 * 32; i += 256) {
        int row = i >> 5, c = i & 31;
        int gr = row0 + row;
        if (gr < NOv) {
            float a = Xs[row * 68 + 2 * c], b = Xs[row * 68 + 2 * c + 1];
            ((half2*)g_xoh)[(long long)gr * 32 + c] = __floats2half2_rn(a, b);
        }
    }
    unsigned long long acc2[4][4];
#pragma unroll
    for (int i = 0; i < 4; i++)
#pragma unroll
        for (int j = 0; j < 4; j++) acc2[i][j] = 0ull;
#pragma unroll 8
    for (int k = 0; k < 64; k++) {
        unsigned long long ab[4];
#pragma unroll
        for (int i = 0; i < 4; i++) ab[i] = pack2(Xs[(ty * 4 + i) * 68 + k]);
        const float* wrow = Wcs + k * 128;
        unsigned long long b0 = *(const unsigned long long*)(wrow + tx * 4);
        unsigned long long b1 = *(const unsigned long long*)(wrow + tx * 4 + 2);
        unsigned long long b2 = *(const unsigned long long*)(wrow + 64 + tx * 4);
        unsigned long long b3 = *(const unsigned long long*)(wrow + 64 + tx * 4 + 2);
#pragma unroll
        for (int i = 0; i < 4; i++) {
            acc2[i][0] = fma2(ab[i], b0, acc2[i][0]);
            acc2[i][1] = fma2(ab[i], b1, acc2[i][1]);
            acc2[i][2] = fma2(ab[i], b2, acc2[i][2]);
            acc2[i][3] = fma2(ab[i], b3, acc2[i][3]);
        }
    }
#pragma unroll
    for (int i = 0; i < 4; i++) {
        int gr = row0 + ty * 4 + i;
        if (gr < NOv) {
            half2* dst = (half2*)g_Oh + (long long)gr * 64;
            float2 p0 = unpack2(acc2[i][0]);
            float2 p1 = unpack2(acc2[i][1]);
            float2 p2 = unpack2(acc2[i][2]);
            float2 p3 = unpack2(acc2[i][3]);
            dst[tx * 2]          = __floats2half2_rn(p0.x, p0.y);
            dst[tx * 2 + 1]      = __floats2half2_rn(p1.x, p1.y);
            dst[32 + tx * 2]     = __floats2half2_rn(p2.x, p2.y);
            dst[32 + tx * 2 + 1] = __floats2half2_rn(p3.x, p3.y);
        }
    }
}

// ---------------- fused attention + edge scoring: one CTA per rider ----------------
__global__ void __launch_bounds__(256) k_fused(
    const float* __restrict__ Wv, const float* __restrict__ bv,
    const float* __restrict__ We, const float* __restrict__ Wp,
    const float* __restrict__ bp, const float* __restrict__ W1,
    const float* __restrict__ W2, const float* __restrict__ b2,
    float* __restrict__ out) {
    int r = blockIdx.x, tid = threadIdx.x;
    int lane = tid & 31, warp = tid >> 5;
    __shared__ __align__(16) float As[64];
    __shared__ __align__(16) float qWes[4];
    __shared__ float c1s;
    __shared__ __align__(16) float wsum[8][64];
    __shared__ __align__(16) float wsc[8][8];
    __shared__ __align__(16) float xs_s[64];
    __shared__ __align__(16) float remb_s[64];
    __shared__ __align__(16) float eas[4];
    __shared__ float asum_s;
    __shared__ __align__(16) float Rcs[128];
    __shared__ __align__(16) float W2s[128];
    __shared__ __align__(16) float Wpre_s[64];
    __shared__ float c2s;
    if (tid < 64) As[tid] = g_A[r * 64 + tid];
    if (tid < 4)  qWes[tid] = g_qWe[r * 4 + tid];
    if (tid == 0) c1s = g_c1[r];
    if (tid < 128) W2s[tid] = W2[tid];
    __syncthreads();
    float2 a2 = ((const float2*)As)[lane];  // dims 2l, 2l+1
    float q0 = qWes[0], q1 = qWes[1], q2 = qWes[2], q3 = qWes[3], c1 = c1s;
    int start = g_starts[r], cnt = g_counts[r];

    // ---- phase 1: attention (fp16 x gathers) ----
    float xs0 = 0.f, xs1 = 0.f;
    float asum = 0.f, e0 = 0.f, e1 = 0.f, e2 = 0.f, e3 = 0.f;
    for (int i = warp; i < cnt; i += 8) {
        const Rec* rp = &g_rec[start + i];
        int o = __ldg(&rp->o);               // broadcast
        float4 ea = __ldg(&rp->ea);          // broadcast, same sector
        unsigned xu = __ldg((const unsigned*)g_xoh + (long long)o * 32 + lane);
        float2 xf = __half22float2(*(const half2*)&xu);
        float pd = xf.x * a2.x + xf.y * a2.y;
        pd += __shfl_xor_sync(0xffffffffu, pd, 16);
        pd += __shfl_xor_sync(0xffffffffu, pd, 8);
        pd += __shfl_xor_sync(0xffffffffu, pd, 4);
        pd += __shfl_xor_sync(0xffffffffu, pd, 2);
        pd += __shfl_xor_sync(0xffffffffu, pd, 1);
        float dot = pd + c1 + ea.x * q0 + ea.y * q1 + ea.z * q2 + ea.w * q3;
        float w = __expf(0.125f * dot);  // softmax shift-invariance: no max needed
        asum += w;
        e0 += w * ea.x; e1 += w * ea.y; e2 += w * ea.z; e3 += w * ea.w;
        xs0 += w * xf.x; xs1 += w * xf.y;
    }
    wsum[warp][2 * lane] = xs0;
    wsum[warp][2 * lane + 1] = xs1;
    if (lane == 0) {
        wsc[warp][0] = asum; wsc[warp][1] = e0; wsc[warp][2] = e1;
        wsc[warp][3] = e2;   wsc[warp][4] = e3;
    }
    __syncthreads();
    if (tid < 64) {
        float v = 0.f;
#pragma unroll
        for (int w = 0; w < 8; w++) v += wsum[w][tid];
        xs_s[tid] = v;
    }
    if (tid < 5) {
        float v = 0.f;
#pragma unroll
        for (int w = 0; w < 8; w++) v += wsc[w][tid];
        if (tid == 0) asum_s = v; else eas[tid - 1] = v;
    }
    __syncthreads();
    if (tid < 64) {
        int h = tid;
        float t = asum_s * bv[h];
#pragma unroll 8
        for (int d = 0; d < 64; d++) t += xs_s[d] * Wv[d * 64 + h];
        t += eas[0] * We[h] + eas[1] * We[64 + h] + eas[2] * We[128 + h] + eas[3] * We[192 + h];
        remb_s[h] = t / (asum_s + 1e-16f) + g_rskip[r * 64 + h];
    }
    __syncthreads();
    if (tid < 128) {
        float acc = g_cvec[tid];
#pragma unroll 8
        for (int h = 0; h < 64; h++) acc += remb_s[h] * W1[(64 + h) * 128 + tid];
        Rcs[tid] = acc;
    }
    if (tid < 64) {
        float acc = 0.f;
#pragma unroll 8
        for (int h = 0; h < 64; h++) acc += Wp[tid * 64 + h] * remb_s[h];
        Wpre_s[tid] = acc;
    }
    if (tid == 0) {
        float acc = 0.f;
        for (int h = 0; h < 64; h++) acc += bp[h] * remb_s[h];
        c2s = acc;
    }
    __syncthreads();

    // ---- phase 2: score this rider's edges ----
    float4 w4 = ((const float4*)W2s)[lane];   // hidden dims 4l..4l+3
    float4 rc4 = ((const float4*)Rcs)[lane];
    float2 p2 = ((const float2*)Wpre_s)[lane];  // dims 2l, 2l+1
    float tail = 0.125f * c2s + __ldg(b2);
    for (int i = warp; i < cnt; i += 8) {
        const Rec* rp = &g_rec[start + i];
        int2 hdr = __ldg((const int2*)rp);   // {o, e} broadcast
        int o = hdr.x, e = hdr.y;
        uint2 Ou = __ldg((const uint2*)g_Oh + (long long)o * 32 + lane);
        unsigned xu = __ldg((const unsigned*)g_xoh + (long long)o * 32 + lane);
        float2 oA = __half22float2(*(const half2*)&Ou.x);
        float2 oB = __half22float2(*(const half2*)&Ou.y);
        float2 xf = __half22float2(*(const half2*)&xu);
        float part = 0.125f * (xf.x * p2.x + xf.y * p2.y);
        part += fmaxf(oA.x + rc4.x, 0.f) * w4.x;
        part += fmaxf(oA.y + rc4.y, 0.f) * w4.y;
        part += fmaxf(oB.x + rc4.z, 0.f) * w4.z;
        part += fmaxf(oB.y + rc4.w, 0.f) * w4.w;
        part += __shfl_xor_sync(0xffffffffu, part, 16);
        part += __shfl_xor_sync(0xffffffffu, part, 8);
        part += __shfl_xor_sync(0xffffffffu, part, 4);
        part += __shfl_xor_sync(0xffffffffu, part, 2);
        part += __shfl_xor_sync(0xffffffffu, part, 1);
        if (lane == 0) {
            float v = part + tail;
            out[e] = fminf(fmaxf(v, -10.f), 10.f);
        }
    }
}

// ---------------- launch ----------------
extern "C" void kernel_launch(void* const* d_in, const int* in_sizes, int n_in,
                              void* d_out, int out_size) {
    const float* xo   = (const float*)d_in[0];
    const float* xr   = (const float*)d_in[1];
    const float* eat  = (const float*)d_in[2];
    const int*   oidx = (const int*)d_in[3];
    const int*   ridx = (const int*)d_in[4];
    const float* omg  = (const float*)d_in[5];
    const float* Wk   = (const float*)d_in[6];
    const float* bk   = (const float*)d_in[7];
    const float* Wq   = (const float*)d_in[8];
    const float* bq   = (const float*)d_in[9];
    const float* Wv   = (const float*)d_in[10];
    const float* bv   = (const float*)d_in[11];
    const float* We   = (const float*)d_in[12];
    const float* Wsk  = (const float*)d_in[13];
    const float* bsk  = (const float*)d_in[14];
    const float* Wp   = (const float*)d_in[15];
    const float* bp   = (const float*)d_in[16];
    const float* W1   = (const float*)d_in[17];
    const float* b1   = (const float*)d_in[18];
    const float* W2   = (const float*)d_in[19];
    const float* b2   = (const float*)d_in[20];
    float* out = (float*)d_out;
    int NOv = in_sizes[0] / 64;
    int NRv = in_sizes[1] / 32;
    int E   = in_sizes[3];

    const int kO_smem = (64 * 68 + 64 * 128) * 4;  // 50176 B
    cudaFuncSetAttribute(k_O, cudaFuncAttributeMaxDynamicSharedMemorySize, kO_smem);

    k_pre<<<NRv + 66, 128>>>(xr, Wq, bq, Wk, bk, We, Wsk, bsk, omg, W1, b1, bp, Wp, NRv);
    k_hist<<<256, 256>>>(ridx, E, NRv);
    k_scan<<<1, 1024>>>(NRv);
    k_scatter<<<512, 256>>>(ridx, oidx, eat, E);  // profiled slot
    k_O<<<(NOv + 63) / 64, dim3(16, 16), kO_smem>>>(xo, NOv);
    k_fused<<<NRv, 256>>>(Wv, bv, We, Wp, bp, W1, W2, b2, out);
}

// round 7
// speedup vs baseline: 1.5618x; 1.5250x over previous
#include <cuda_runtime.h>
#include <cuda_fp16.h>

#define NO_MAX 100000
#define NR_MAX 1000
#define E_MAX  1000000

struct __align__(16) Rec { int o; int e; int pad0; int pad1; float4 ea; };  // 32B

// ---------------- scratch (device globals; no allocations) ----------------
__device__ float g_A[NR_MAX * 64];
__device__ float g_c1[NR_MAX];
__device__ float g_qWe[NR_MAX * 4];
__device__ float g_rskip[NR_MAX * 64];
__device__ float g_Wc[64 * 128];
__device__ float g_cvec[128];
__device__ int   g_cnt_pad[NR_MAX * 32];    // zero at start of every replay (scan clears)
__device__ int   g_cursor_pad[NR_MAX * 32];
__device__ int   g_counts[NR_MAX];
__device__ int   g_starts[NR_MAX];
__device__ __align__(16) Rec g_rec[E_MAX];
__device__ __align__(16) __half g_Oh[(long long)NO_MAX * 128];
__device__ __align__(16) __half g_xoh[(long long)NO_MAX * 64];

__device__ __forceinline__ unsigned long long fma2(unsigned long long a,
                                                   unsigned long long b,
                                                   unsigned long long c) {
    unsigned long long d;
    asm("fma.rn.f32x2 %0, %1, %2, %3;" : "=l"(d) : "l"(a), "l"(b), "l"(c));
    return d;
}
__device__ __forceinline__ unsigned long long pack2(float x) {
    unsigned long long d;
    asm("mov.b64 %0, {%1, %1};" : "=l"(d) : "r"(__float_as_uint(x)));
    return d;
}
__device__ __forceinline__ float2 unpack2(unsigned long long v) {
    unsigned lo, hi;
    asm("mov.b64 {%0, %1}, %2;" : "=r"(lo), "=r"(hi) : "l"(v));
    return make_float2(__uint_as_float(lo), __uint_as_float(hi));
}

// ---------------- launch 1: rider precompute + const + Wc + histogram ----------------
__global__ void __launch_bounds__(128) k_preh(
    const float* __restrict__ xr,
    const float* __restrict__ Wq, const float* __restrict__ bq,
    const float* __restrict__ Wk, const float* __restrict__ bk,
    const float* __restrict__ We,
    const float* __restrict__ Wsk, const float* __restrict__ bsk,
    const float* __restrict__ omg, const float* __restrict__ W1,
    const float* __restrict__ b1, const float* __restrict__ bp,
    const float* __restrict__ Wp, const int* __restrict__ ridx,
    int NRv, int E) {
    int b = blockIdx.x, h = threadIdx.x;
    if (b < NRv) {
        int r = b;
        __shared__ float xs[32], qs[64];
        if (h < 32) xs[h] = xr[r * 32 + h];
        __syncthreads();
        if (h < 64) {
            float q = bq[h];
#pragma unroll 8
            for (int d = 0; d < 32; d++) q += xs[d] * Wq[d * 64 + h];
            qs[h] = q;
            float sk = bsk[h];
#pragma unroll 8
            for (int d = 0; d < 32; d++) sk += xs[d] * Wsk[d * 64 + h];
            g_rskip[r * 64 + h] = sk;
        }
        __syncthreads();
        if (h < 64) {
            float a = 0.f;
#pragma unroll 8
            for (int t = 0; t < 64; t++) a += Wk[h * 64 + t] * qs[t];
            g_A[r * 64 + h] = a;
        }
        if (h < 4) {
            float w = 0.f;
            for (int t = 0; t < 64; t++) w += We[h * 64 + t] * qs[t];
            g_qWe[r * 4 + h] = w;
        }
        if (h == 0) {
            float c = 0.f;
            for (int t = 0; t < 64; t++) c += bk[t] * qs[t];
            g_c1[r] = c;
        }
    } else if (b == NRv) {
        float c = b1[h];
        for (int m = 0; m < 32; m++) c += omg[m] * W1[(128 + m) * 128 + h];
        for (int d = 0; d < 64; d++) c += bp[d] * W1[d * 128 + h];
        g_cvec[h] = c;
    } else if (b < NRv + 65) {
        int d = b - NRv - 1;
        __shared__ float wp[64];
        if (h < 64) wp[h] = Wp[d * 64 + h];
        __syncthreads();
        float acc = 0.f;
#pragma unroll 8
        for (int t = 0; t < 64; t++) acc += wp[t] * W1[t * 128 + h];
        g_Wc[d * 128 + h] = acc;
    } else {
        // histogram blocks
        int hb = b - (NRv + 65);           // 0..255
        __shared__ int sh[NR_MAX];
        for (int i = h; i < NRv; i += 128) sh[i] = 0;
        __syncthreads();
        for (int e = hb * 128 + h; e < E; e += 256 * 128)
            atomicAdd(&sh[ridx[e]], 1);
        __syncthreads();
        for (int i = h; i < NRv; i += 128) {
            int c = sh[i];
            if (c) atomicAdd(&g_cnt_pad[i * 32], c);
        }
    }
}

// ---------------- launch 2: scan (reads counters, then clears them for next replay) ----------------
__global__ void k_scan(int NRv) {
    __shared__ int s[1024];
    int t = threadIdx.x;
    int v = (t < NRv) ? g_cnt_pad[t * 32] : 0;
    if (t < NRv) g_cnt_pad[t * 32] = 0;   // self-restore for graph replay
    s[t] = v;
    __syncthreads();
    for (int off = 1; off < 1024; off <<= 1) {
        int u = (t >= off) ? s[t - off] : 0;
        __syncthreads();
        s[t] += u;
        __syncthreads();
    }
    if (t < NRv) {
        int st = s[t] - v;
        g_starts[t] = st;
        g_counts[t] = v;
        g_cursor_pad[t * 32] = st;
    }
}

// ---------------- launch 3: O-GEMM tiles + scatter blocks (branched) ----------------
__global__ void __launch_bounds__(256) k_Oscat(
    const float* __restrict__ xo, int NOv, int NOt,
    const int* __restrict__ ridx, const int* __restrict__ oidx,
    const float* __restrict__ eat, int E) {
    int tid = threadIdx.x;
    if ((int)blockIdx.x >= NOt) {
        // scatter branch
        int b = blockIdx.x - NOt;
        for (int e = b * 256 + tid; e < E; e += 512 * 256) {
            int r = ridx[e];
            int pos = atomicAdd(&g_cursor_pad[r * 32], 1);
            Rec* rp = &g_rec[pos];
            *(int4*)rp = make_int4(oidx[e], e, 0, 0);
            rp->ea = ((const float4*)eat)[e];
        }
        return;
    }
    extern __shared__ __align__(16) float dsm[];
    float* Xs  = dsm;            // [64][68]
    float* Wcs = dsm + 64 * 68;  // [64][128]
    int tx = tid & 15, ty = tid >> 4;
    int row0 = blockIdx.x * 64;
    for (int i = tid; i < 64 * 32; i += 256)
        ((float4*)Wcs)[i] = ((const float4*)g_Wc)[i];
    for (int i = tid; i < 64 * 16; i += 256) {
        int row = i >> 4, kq = i & 15;
        float4 xv = make_float4(0.f, 0.f, 0.f, 0.f);
        int gr = row0 + row;
        if (gr < NOv) xv = ((const float4*)xo)[gr * 16 + kq];
        *((float4*)(Xs + row * 68 + kq * 4)) = xv;
    }
    __syncthreads();
    for (int i = tid; i < 64 * 32; i += 256) {
        int row = i >> 5, c = i & 31;
        int gr = row0 + row;
        if (gr < NOv) {
            float a = Xs[row * 68 + 2 * c], b = Xs[row * 68 + 2 * c + 1];
            ((half2*)g_xoh)[(long long)gr * 32 + c] = __floats2half2_rn(a, b);
        }
    }
    unsigned long long acc2[4][4];
#pragma unroll
    for (int i = 0; i < 4; i++)
#pragma unroll
        for (int j = 0; j < 4; j++) acc2[i][j] = 0ull;
#pragma unroll 8
    for (int k = 0; k < 64; k++) {
        unsigned long long ab[4];
#pragma unroll
        for (int i = 0; i < 4; i++) ab[i] = pack2(Xs[(ty * 4 + i) * 68 + k]);
        const float* wrow = Wcs + k * 128;
        unsigned long long b0 = *(const unsigned long long*)(wrow + tx * 4);
        unsigned long long b1 = *(const unsigned long long*)(wrow + tx * 4 + 2);
        unsigned long long b2 = *(const unsigned long long*)(wrow + 64 + tx * 4);
        unsigned long long b3 = *(const unsigned long long*)(wrow + 64 + tx * 4 + 2);
#pragma unroll
        for (int i = 0; i < 4; i++) {
            acc2[i][0] = fma2(ab[i], b0, acc2[i][0]);
            acc2[i][1] = fma2(ab[i], b1, acc2[i][1]);
            acc2[i][2] = fma2(ab[i], b2, acc2[i][2]);
            acc2[i][3] = fma2(ab[i], b3, acc2[i][3]);
        }
    }
#pragma unroll
    for (int i = 0; i < 4; i++) {
        int gr = row0 + ty * 4 + i;
        if (gr < NOv) {
            half2* dst = (half2*)g_Oh + (long long)gr * 64;
            float2 p0 = unpack2(acc2[i][0]);
            float2 p1 = unpack2(acc2[i][1]);
            float2 p2 = unpack2(acc2[i][2]);
            float2 p3 = unpack2(acc2[i][3]);
            dst[tx * 2]          = __floats2half2_rn(p0.x, p0.y);
            dst[tx * 2 + 1]      = __floats2half2_rn(p1.x, p1.y);
            dst[32 + tx * 2]     = __floats2half2_rn(p2.x, p2.y);
            dst[32 + tx * 2 + 1] = __floats2half2_rn(p3.x, p3.y);
        }
    }
}

// ---------------- launch 4: fused attention + edge scoring (8-lane groups, 4 edges/warp-iter) ----
__global__ void __launch_bounds__(256) k_fused(
    const float* __restrict__ Wv, const float* __restrict__ bv,
    const float* __restrict__ We, const float* __restrict__ Wp,
    const float* __restrict__ bp, const float* __restrict__ W1,
    const float* __restrict__ W2, const float* __restrict__ b2,
    float* __restrict__ out) {
    int r = blockIdx.x, tid = threadIdx.x;
    int lane = tid & 31, warp = tid >> 5;
    int g = lane >> 3, j = lane & 7;   // 4 groups of 8 lanes
    __shared__ __align__(16) float As[64];
    __shared__ __align__(16) float qWes[4];
    __shared__ float c1s;
    __shared__ __align__(16) float wsum[8][64];
    __shared__ __align__(16) float wsc[8][8];
    __shared__ __align__(16) float xs_s[64];
    __shared__ __align__(16) float remb_s[64];
    __shared__ __align__(16) float eas[4];
    __shared__ float asum_s;
    __shared__ __align__(16) float Rcs[128];
    __shared__ __align__(16) float W2s[128];
    __shared__ __align__(16) float Wpre_s[64];
    __shared__ float c2s;
    if (tid < 64) As[tid] = g_A[r * 64 + tid];
    if (tid < 4)  qWes[tid] = g_qWe[r * 4 + tid];
    if (tid == 0) c1s = g_c1[r];
    if (tid < 128) W2s[tid] = W2[tid];
    __syncthreads();
    int start = g_starts[r], cnt = g_counts[r];
    float q0 = qWes[0], q1 = qWes[1], q2 = qWes[2], q3 = qWes[3], c1 = c1s;

    // per-lane A slice: dims 8j..8j+7
    float a8[8];
#pragma unroll
    for (int k = 0; k < 8; k++) a8[k] = As[8 * j + k];

    // ---- phase 1: attention ----
    float xs8[8];
#pragma unroll
    for (int k = 0; k < 8; k++) xs8[k] = 0.f;
    float asum = 0.f, e0 = 0.f, e1 = 0.f, e2 = 0.f, e3 = 0.f;
    for (int base = warp * 4; base < cnt; base += 32) {
        int i = base + g;
        bool valid = i < cnt;
        int idx = start + (valid ? i : 0);
        const Rec* rp = &g_rec[idx];
        int o = __ldg(&rp->o);
        float4 ea = __ldg(&rp->ea);
        uint4 xq = __ldg((const uint4*)(g_xoh + (long long)o * 64) + j);
        float2 x0 = __half22float2(*(const half2*)&xq.x);
        float2 x1 = __half22float2(*(const half2*)&xq.y);
        float2 x2 = __half22float2(*(const half2*)&xq.z);
        float2 x3 = __half22float2(*(const half2*)&xq.w);
        float pd = x0.x * a8[0] + x0.y * a8[1] + x1.x * a8[2] + x1.y * a8[3]
                 + x2.x * a8[4] + x2.y * a8[5] + x3.x * a8[6] + x3.y * a8[7];
        pd += __shfl_xor_sync(0xffffffffu, pd, 1);
        pd += __shfl_xor_sync(0xffffffffu, pd, 2);
        pd += __shfl_xor_sync(0xffffffffu, pd, 4);
        float dot = pd + c1 + ea.x * q0 + ea.y * q1 + ea.z * q2 + ea.w * q3;
        float w = valid ? __expf(0.125f * dot) : 0.f;  // shift-invariant softmax
        asum += w;
        e0 += w * ea.x; e1 += w * ea.y; e2 += w * ea.z; e3 += w * ea.w;
        xs8[0] += w * x0.x; xs8[1] += w * x0.y;
        xs8[2] += w * x1.x; xs8[3] += w * x1.y;
        xs8[4] += w * x2.x; xs8[5] += w * x2.y;
        xs8[6] += w * x3.x; xs8[7] += w * x3.y;
    }
    // reduce xs8 across the 4 groups (lanes j, j+8, j+16, j+24 share dims)
#pragma unroll
    for (int k = 0; k < 8; k++) {
        float v = xs8[k];
        v += __shfl_xor_sync(0xffffffffu, v, 8);
        v += __shfl_xor_sync(0xffffffffu, v, 16);
        xs8[k] = v;
    }
    if (lane < 8) {
#pragma unroll
        for (int k = 0; k < 8; k++) wsum[warp][lane * 8 + k] = xs8[k];
    }
    // scalars: every lane of a group holds the group's sum -> full butterfly counts x8
    float sc[5] = {asum, e0, e1, e2, e3};
#pragma unroll
    for (int m = 0; m < 5; m++) {
        float v = sc[m];
        v += __shfl_xor_sync(0xffffffffu, v, 16);
        v += __shfl_xor_sync(0xffffffffu, v, 8);
        v += __shfl_xor_sync(0xffffffffu, v, 4);
        v += __shfl_xor_sync(0xffffffffu, v, 2);
        v += __shfl_xor_sync(0xffffffffu, v, 1);
        sc[m] = v * 0.125f;  // each edge counted by 8 lanes
    }
    if (lane == 0) {
#pragma unroll
        for (int m = 0; m < 5; m++) wsc[warp][m] = sc[m];
    }
    __syncthreads();
    if (tid < 64) {
        float v = 0.f;
#pragma unroll
        for (int w = 0; w < 8; w++) v += wsum[w][tid];
        xs_s[tid] = v;
    }
    if (tid < 5) {
        float v = 0.f;
#pragma unroll
        for (int w = 0; w < 8; w++) v += wsc[w][tid];
        if (tid == 0) asum_s = v; else eas[tid - 1] = v;
    }
    __syncthreads();
    if (tid < 64) {
        int h = tid;
        float t = asum_s * bv[h];
#pragma unroll 8
        for (int d = 0; d < 64; d++) t += xs_s[d] * Wv[d * 64 + h];
        t += eas[0] * We[h] + eas[1] * We[64 + h] + eas[2] * We[128 + h] + eas[3] * We[192 + h];
        remb_s[h] = t / (asum_s + 1e-16f) + g_rskip[r * 64 + h];
    }
    __syncthreads();
    if (tid < 128) {
        float acc = g_cvec[tid];
#pragma unroll 8
        for (int h = 0; h < 64; h++) acc += remb_s[h] * W1[(64 + h) * 128 + tid];
        Rcs[tid] = acc;
    }
    if (tid < 64) {
        float acc = 0.f;
#pragma unroll 8
        for (int h = 0; h < 64; h++) acc += Wp[tid * 64 + h] * remb_s[h];
        Wpre_s[tid] = acc;
    }
    if (tid == 0) {
        float acc = 0.f;
        for (int h = 0; h < 64; h++) acc += bp[h] * remb_s[h];
        c2s = acc;
    }
    __syncthreads();

    // ---- phase 2: score edges, 8-lane groups ----
    // lane j covers hidden dims 16j..16j+15 and x-dims 8j..8j+7
    float rc16[16], w216[16], p8[8];
#pragma unroll
    for (int k = 0; k < 16; k++) { rc16[k] = Rcs[16 * j + k]; w216[k] = W2s[16 * j + k]; }
#pragma unroll
    for (int k = 0; k < 8; k++) p8[k] = Wpre_s[8 * j + k];
    float tail = 0.125f * c2s + __ldg(b2);
    for (int base = warp * 4; base < cnt; base += 32) {
        int i = base + g;
        bool valid = i < cnt;
        int idx = start + (valid ? i : 0);
        const Rec* rp = &g_rec[idx];
        int2 hdr = __ldg((const int2*)rp);
        int o = hdr.x, e = hdr.y;
        const uint4* Orow = (const uint4*)(g_Oh + (long long)o * 128);
        uint4 O0 = __ldg(Orow + 2 * j);
        uint4 O1 = __ldg(Orow + 2 * j + 1);
        uint4 xq = __ldg((const uint4*)(g_xoh + (long long)o * 64) + j);
        float part = 0.f;
        {
            float2 f;
            f = __half22float2(*(const half2*)&O0.x);
            part += fmaxf(f.x + rc16[0], 0.f) * w216[0] + fmaxf(f.y + rc16[1], 0.f) * w216[1];
            f = __half22float2(*(const half2*)&O0.y);
            part += fmaxf(f.x + rc16[2], 0.f) * w216[2] + fmaxf(f.y + rc16[3], 0.f) * w216[3];
            f = __half22float2(*(const half2*)&O0.z);
            part += fmaxf(f.x + rc16[4], 0.f) * w216[4] + fmaxf(f.y + rc16[5], 0.f) * w216[5];
            f = __half22float2(*(const half2*)&O0.w);
            part += fmaxf(f.x + rc16[6], 0.f) * w216[6] + fmaxf(f.y + rc16[7], 0.f) * w216[7];
            f = __half22float2(*(const half2*)&O1.x);
            part += fmaxf(f.x + rc16[8], 0.f) * w216[8] + fmaxf(f.y + rc16[9], 0.f) * w216[9];
            f = __half22float2(*(const half2*)&O1.y);
            part += fmaxf(f.x + rc16[10], 0.f) * w216[10] + fmaxf(f.y + rc16[11], 0.f) * w216[11];
            f = __half22float2(*(const half2*)&O1.z);
            part += fmaxf(f.x + rc16[12], 0.f) * w216[12] + fmaxf(f.y + rc16[13], 0.f) * w216[13];
            f = __half22float2(*(const half2*)&O1.w);
            part += fmaxf(f.x + rc16[14], 0.f) * w216[14] + fmaxf(f.y + rc16[15], 0.f) * w216[15];
        }
        {
            float2 x0 = __half22float2(*(const half2*)&xq.x);
            float2 x1 = __half22float2(*(const half2*)&xq.y);
            float2 x2 = __half22float2(*(const half2*)&xq.z);
            float2 x3 = __half22float2(*(const half2*)&xq.w);
            float d = x0.x * p8[0] + x0.y * p8[1] + x1.x * p8[2] + x1.y * p8[3]
                    + x2.x * p8[4] + x2.y * p8[5] + x3.x * p8[6] + x3.y * p8[7];
            part += 0.125f * d;
        }
        part += __shfl_xor_sync(0xffffffffu, part, 1);
        part += __shfl_xor_sync(0xffffffffu, part, 2);
        part += __shfl_xor_sync(0xffffffffu, part, 4);
        if (j == 0 && valid) {
            float v = part + tail;
            out[e] = fminf(fmaxf(v, -10.f), 10.f);
        }
    }
}

// ---------------- launch ----------------
extern "C" void kernel_launch(void* const* d_in, const int* in_sizes, int n_in,
                              void* d_out, int out_size) {
    const float* xo   = (const float*)d_in[0];
    const float* xr   = (const float*)d_in[1];
    const float* eat  = (const float*)d_in[2];
    const int*   oidx = (const int*)d_in[3];
    const int*   ridx = (const int*)d_in[4];
    const float* omg  = (const float*)d_in[5];
    const float* Wk   = (const float*)d_in[6];
    const float* bk   = (const float*)d_in[7];
    const float* Wq   = (const float*)d_in[8];
    const float* bq   = (const float*)d_in[9];
    const float* Wv   = (const float*)d_in[10];
    const float* bv   = (const float*)d_in[11];
    const float* We   = (const float*)d_in[12];
    const float* Wsk  = (const float*)d_in[13];
    const float* bsk  = (const float*)d_in[14];
    const float* Wp   = (const float*)d_in[15];
    const float* bp   = (const float*)d_in[16];
    const float* W1   = (const float*)d_in[17];
    const float* b1   = (const float*)d_in[18];
    const float* W2   = (const float*)d_in[19];
    const float* b2   = (const float*)d_in[20];
    float* out = (float*)d_out;
    int NOv = in_sizes[0] / 64;
    int NRv = in_sizes[1] / 32;
    int E   = in_sizes[3];
    int NOt = (NOv + 63) / 64;

    const int kO_smem = (64 * 68 + 64 * 128) * 4;  // 50176 B
    cudaFuncSetAttribute(k_Oscat, cudaFuncAttributeMaxDynamicSharedMemorySize, kO_smem);

    k_preh<<<NRv + 65 + 256, 128>>>(xr, Wq, bq, Wk, bk, We, Wsk, bsk,
                                    omg, W1, b1, bp, Wp, ridx, NRv, E);
    k_scan<<<1, 1024>>>(NRv);
    k_Oscat<<<NOt + 512, 256, kO_smem>>>(xo, NOv, NOt, ridx, oidx, eat, E);
    k_fused<<<NRv, 256>>>(Wv, bv, We, Wp, bp, W1, W2, b2, out);
}

// round 8
// speedup vs baseline: 1.8331x; 1.1737x over previous
#include <cuda_runtime.h>
#include <cuda_fp16.h>

#define NO_MAX 100000
#define NR_MAX 1000
#define E_MAX  1000000

struct __align__(16) Rec { int o; int e; int r; int pad1; float4 ea; };  // 32B

// ---------------- scratch (device globals; no allocations) ----------------
__device__ float g_A[NR_MAX * 64];
__device__ float g_c1[NR_MAX];
__device__ float g_qWe[NR_MAX * 4];
__device__ float g_rskip[NR_MAX * 64];
__device__ float g_Wc[64 * 128];
__device__ float g_cvec[128];
__device__ int   g_cnt_pad[NR_MAX * 32];
__device__ int   g_cursor_pad[NR_MAX * 32];
__device__ int   g_counts[NR_MAX];
__device__ int   g_starts[NR_MAX];
__device__ float g_acc[NR_MAX * 128];     // [r*128+0..63]=xsum, [64]=asum, [65..68]=ea sums
__device__ float g_c2[NR_MAX];
__device__ __align__(16) Rec g_rec[E_MAX];
__device__ __align__(16) __half g_Oh[(long long)NO_MAX * 128];
__device__ __align__(16) __half g_xoh[(long long)NO_MAX * 64];
__device__ __align__(16) __half g_Rch[NR_MAX * 128];
__device__ __align__(16) __half g_Wpreh[NR_MAX * 64];

__device__ __forceinline__ unsigned long long fma2(unsigned long long a,
                                                   unsigned long long b,
                                                   unsigned long long c) {
    unsigned long long d;
    asm("fma.rn.f32x2 %0, %1, %2, %3;" : "=l"(d) : "l"(a), "l"(b), "l"(c));
    return d;
}
__device__ __forceinline__ unsigned long long pack2(float x) {
    unsigned long long d;
    asm("mov.b64 %0, {%1, %1};" : "=l"(d) : "r"(__float_as_uint(x)));
    return d;
}
__device__ __forceinline__ float2 unpack2(unsigned long long v) {
    unsigned lo, hi;
    asm("mov.b64 {%0, %1}, %2;" : "=r"(lo), "=r"(hi) : "l"(v));
    return make_float2(__uint_as_float(lo), __uint_as_float(hi));
}

// ---------------- launch 1: rider precompute + const + Wc + histogram + acc-zero ----------------
__global__ void __launch_bounds__(128) k_preh(
    const float* __restrict__ xr,
    const float* __restrict__ Wq, const float* __restrict__ bq,
    const float* __restrict__ Wk, const float* __restrict__ bk,
    const float* __restrict__ We,
    const float* __restrict__ Wsk, const float* __restrict__ bsk,
    const float* __restrict__ omg, const float* __restrict__ W1,
    const float* __restrict__ b1, const float* __restrict__ bp,
    const float* __restrict__ Wp, const int* __restrict__ ridx,
    int NRv, int E) {
    int b = blockIdx.x, h = threadIdx.x;
    if (b < NRv) {
        int r = b;
        __shared__ float xs[32], qs[64];
        if (h < 32) xs[h] = xr[r * 32 + h];
        __syncthreads();
        if (h < 64) {
            float q = bq[h];
#pragma unroll 8
            for (int d = 0; d < 32; d++) q += xs[d] * Wq[d * 64 + h];
            qs[h] = q;
            float sk = bsk[h];
#pragma unroll 8
            for (int d = 0; d < 32; d++) sk += xs[d] * Wsk[d * 64 + h];
            g_rskip[r * 64 + h] = sk;
        }
        __syncthreads();
        if (h < 64) {
            float a = 0.f;
#pragma unroll 8
            for (int t = 0; t < 64; t++) a += Wk[h * 64 + t] * qs[t];
            g_A[r * 64 + h] = a;
        }
        if (h < 4) {
            float w = 0.f;
            for (int t = 0; t < 64; t++) w += We[h * 64 + t] * qs[t];
            g_qWe[r * 4 + h] = w;
        }
        if (h == 0) {
            float c = 0.f;
            for (int t = 0; t < 64; t++) c += bk[t] * qs[t];
            g_c1[r] = c;
        }
    } else if (b == NRv) {
        float c = b1[h];
        for (int m = 0; m < 32; m++) c += omg[m] * W1[(128 + m) * 128 + h];
        for (int d = 0; d < 64; d++) c += bp[d] * W1[d * 128 + h];
        g_cvec[h] = c;
    } else if (b < NRv + 65) {
        int d = b - NRv - 1;
        __shared__ float wp[64];
        if (h < 64) wp[h] = Wp[d * 64 + h];
        __syncthreads();
        float acc = 0.f;
#pragma unroll 8
        for (int t = 0; t < 64; t++) acc += wp[t] * W1[t * 128 + h];
        g_Wc[d * 128 + h] = acc;
    } else {
        int idx = b - (NRv + 65);
        if (idx < 256) {
            // histogram blocks
            __shared__ int sh[NR_MAX];
            for (int i = h; i < NRv; i += 128) sh[i] = 0;
            __syncthreads();
            for (int e = idx * 128 + h; e < E; e += 256 * 128)
                atomicAdd(&sh[ridx[e]], 1);
            __syncthreads();
            for (int i = h; i < NRv; i += 128) {
                int c = sh[i];
                if (c) atomicAdd(&g_cnt_pad[i * 32], c);
            }
        } else {
            // zero g_acc (graph-replay safe)
            int z = idx - 256;                 // 0..127
            int t = z * 128 + h;               // 0..16383
            for (int i = t; i < NRv * 128; i += 128 * 128) g_acc[i] = 0.f;
        }
    }
}

// ---------------- launch 2: scan (reads counters, then clears for next replay) ----------------
__global__ void k_scan(int NRv) {
    __shared__ int s[1024];
    int t = threadIdx.x;
    int v = (t < NRv) ? g_cnt_pad[t * 32] : 0;
    if (t < NRv) g_cnt_pad[t * 32] = 0;
    s[t] = v;
    __syncthreads();
    for (int off = 1; off < 1024; off <<= 1) {
        int u = (t >= off) ? s[t - off] : 0;
        __syncthreads();
        s[t] += u;
        __syncthreads();
    }
    if (t < NRv) {
        int st = s[t] - v;
        g_starts[t] = st;
        g_counts[t] = v;
        g_cursor_pad[t * 32] = st;
    }
}

// ---------------- launch 3: O-GEMM tiles + scatter blocks ----------------
__global__ void __launch_bounds__(256) k_Oscat(
    const float* __restrict__ xo, int NOv, int NOt,
    const int* __restrict__ ridx, const int* __restrict__ oidx,
    const float* __restrict__ eat, int E) {
    int tid = threadIdx.x;
    if ((int)blockIdx.x >= NOt) {
        int b = blockIdx.x - NOt;
        for (int e = b * 256 + tid; e < E; e += 512 * 256) {
            int r = ridx[e];
            int pos = atomicAdd(&g_cursor_pad[r * 32], 1);
            Rec* rp = &g_rec[pos];
            *(int4*)rp = make_int4(oidx[e], e, r, 0);
            rp->ea = ((const float4*)eat)[e];
        }
        return;
    }
    extern __shared__ __align__(16) float dsm[];
    float* Xs  = dsm;            // [64][68]
    float* Wcs = dsm + 64 * 68;  // [64][128]
    int tx = tid & 15, ty = tid >> 4;
    int row0 = blockIdx.x * 64;
    for (int i = tid; i < 64 * 32; i += 256)
        ((float4*)Wcs)[i] = ((const float4*)g_Wc)[i];
    for (int i = tid; i < 64 * 16; i += 256) {
        int row = i >> 4, kq = i & 15;
        float4 xv = make_float4(0.f, 0.f, 0.f, 0.f);
        int gr = row0 + row;
        if (gr < NOv) xv = ((const float4*)xo)[gr * 16 + kq];
        *((float4*)(Xs + row * 68 + kq * 4)) = xv;
    }
    __syncthreads();
    for (int i = tid; i < 64 * 32; i += 256) {
        int row = i >> 5, c = i & 31;
        int gr = row0 + row;
        if (gr < NOv) {
            float a = Xs[row * 68 + 2 * c], b = Xs[row * 68 + 2 * c + 1];
            ((half2*)g_xoh)[(long long)gr * 32 + c] = __floats2half2_rn(a, b);
        }
    }
    unsigned long long acc2[4][4];
#pragma unroll
    for (int i = 0; i < 4; i++)
#pragma unroll
        for (int j = 0; j < 4; j++) acc2[i][j] = 0ull;
#pragma unroll 8
    for (int k = 0; k < 64; k++) {
        unsigned long long ab[4];
#pragma unroll
        for (int i = 0; i < 4; i++) ab[i] = pack2(Xs[(ty * 4 + i) * 68 + k]);
        const float* wrow = Wcs + k * 128;
        unsigned long long b0 = *(const unsigned long long*)(wrow + tx * 4);
        unsigned long long b1 = *(const unsigned long long*)(wrow + tx * 4 + 2);
        unsigned long long b2 = *(const unsigned long long*)(wrow + 64 + tx * 4);
        unsigned long long b3 = *(const unsigned long long*)(wrow + 64 + tx * 4 + 2);
#pragma unroll
        for (int i = 0; i < 4; i++) {
            acc2[i][0] = fma2(ab[i], b0, acc2[i][0]);
            acc2[i][1] = fma2(ab[i], b1, acc2[i][1]);
            acc2[i][2] = fma2(ab[i], b2, acc2[i][2]);
            acc2[i][3] = fma2(ab[i], b3, acc2[i][3]);
        }
    }
#pragma unroll
    for (int i = 0; i < 4; i++) {
        int gr = row0 + ty * 4 + i;
        if (gr < NOv) {
            half2* dst = (half2*)g_Oh + (long long)gr * 64;
            float2 p0 = unpack2(acc2[i][0]);
            float2 p1 = unpack2(acc2[i][1]);
            float2 p2 = unpack2(acc2[i][2]);
            float2 p3 = unpack2(acc2[i][3]);
            dst[tx * 2]          = __floats2half2_rn(p0.x, p0.y);
            dst[tx * 2 + 1]      = __floats2half2_rn(p1.x, p1.y);
            dst[32 + tx * 2]     = __floats2half2_rn(p2.x, p2.y);
            dst[32 + tx * 2 + 1] = __floats2half2_rn(p3.x, p3.y);
        }
    }
}

// ---------------- launch 4: attention partials (4 CTAs per rider) ----------------
__global__ void __launch_bounds__(256) k_att1() {
    int bid = blockIdx.x;
    int r = bid >> 2, chunk = bid & 3;
    int tid = threadIdx.x, lane = tid & 31, warp = tid >> 5;
    int g = lane >> 3, j = lane & 7;
    __shared__ __align__(16) float wsum[8][64];
    __shared__ __align__(16) float wsc[8][8];
    float a8[8];
#pragma unroll
    for (int k = 0; k < 8; k++) a8[k] = __ldg(g_A + r * 64 + 8 * j + k);
    float q0 = __ldg(g_qWe + r * 4), q1 = __ldg(g_qWe + r * 4 + 1);
    float q2 = __ldg(g_qWe + r * 4 + 2), q3 = __ldg(g_qWe + r * 4 + 3);
    float c1 = __ldg(g_c1 + r);
    int start = g_starts[r], cnt = g_counts[r];

    float xs8[8];
#pragma unroll
    for (int k = 0; k < 8; k++) xs8[k] = 0.f;
    float asum = 0.f, e0 = 0.f, e1 = 0.f, e2 = 0.f, e3 = 0.f;
    for (int base = (chunk * 8 + warp) * 4; base < cnt; base += 128) {
        int i = base + g;
        bool valid = i < cnt;
        const Rec* rp = &g_rec[start + (valid ? i : 0)];
        int o = __ldg(&rp->o);
        float4 ea = __ldg(&rp->ea);
        uint4 xq = __ldg((const uint4*)(g_xoh + (long long)o * 64) + j);
        float2 x0 = __half22float2(*(const half2*)&xq.x);
        float2 x1 = __half22float2(*(const half2*)&xq.y);
        float2 x2 = __half22float2(*(const half2*)&xq.z);
        float2 x3 = __half22float2(*(const half2*)&xq.w);
        float pd = x0.x * a8[0] + x0.y * a8[1] + x1.x * a8[2] + x1.y * a8[3]
                 + x2.x * a8[4] + x2.y * a8[5] + x3.x * a8[6] + x3.y * a8[7];
        pd += __shfl_xor_sync(0xffffffffu, pd, 1);
        pd += __shfl_xor_sync(0xffffffffu, pd, 2);
        pd += __shfl_xor_sync(0xffffffffu, pd, 4);
        float dot = pd + c1 + ea.x * q0 + ea.y * q1 + ea.z * q2 + ea.w * q3;
        float w = valid ? __expf(0.125f * dot) : 0.f;  // shift-invariant softmax
        asum += w;
        e0 += w * ea.x; e1 += w * ea.y; e2 += w * ea.z; e3 += w * ea.w;
        xs8[0] += w * x0.x; xs8[1] += w * x0.y;
        xs8[2] += w * x1.x; xs8[3] += w * x1.y;
        xs8[4] += w * x2.x; xs8[5] += w * x2.y;
        xs8[6] += w * x3.x; xs8[7] += w * x3.y;
    }
#pragma unroll
    for (int k = 0; k < 8; k++) {
        float v = xs8[k];
        v += __shfl_xor_sync(0xffffffffu, v, 8);
        v += __shfl_xor_sync(0xffffffffu, v, 16);
        xs8[k] = v;
    }
    if (lane < 8) {
#pragma unroll
        for (int k = 0; k < 8; k++) wsum[warp][lane * 8 + k] = xs8[k];
    }
    float sc[5] = {asum, e0, e1, e2, e3};
#pragma unroll
    for (int m = 0; m < 5; m++) {
        float v = sc[m];
        v += __shfl_xor_sync(0xffffffffu, v, 16);
        v += __shfl_xor_sync(0xffffffffu, v, 8);
        v += __shfl_xor_sync(0xffffffffu, v, 4);
        v += __shfl_xor_sync(0xffffffffu, v, 2);
        v += __shfl_xor_sync(0xffffffffu, v, 1);
        sc[m] = v * 0.125f;  // each edge counted by 8 lanes
    }
    if (lane == 0) {
#pragma unroll
        for (int m = 0; m < 5; m++) wsc[warp][m] = sc[m];
    }
    __syncthreads();
    if (tid < 64) {
        float v = 0.f;
#pragma unroll
        for (int w = 0; w < 8; w++) v += wsum[w][tid];
        atomicAdd(&g_acc[r * 128 + tid], v);
    }
    if (tid >= 64 && tid < 69) {
        int m = tid - 64;
        float v = 0.f;
#pragma unroll
        for (int w = 0; w < 8; w++) v += wsc[w][m];
        atomicAdd(&g_acc[r * 128 + 64 + m], v);
    }
}

// ---------------- launch 5: per-rider finish ----------------
__global__ void __launch_bounds__(128) k_rider(
    const float* __restrict__ Wv, const float* __restrict__ bv,
    const float* __restrict__ We, const float* __restrict__ Wp,
    const float* __restrict__ bp, const float* __restrict__ W1) {
    int r = blockIdx.x, tid = threadIdx.x;
    __shared__ __align__(16) float xs_s[64];
    __shared__ __align__(16) float remb_s[64];
    __shared__ __align__(16) float eas[4];
    __shared__ float asum_s;
    if (tid < 64) xs_s[tid] = g_acc[r * 128 + tid];
    if (tid == 64) asum_s = g_acc[r * 128 + 64];
    if (tid > 64 && tid < 69) eas[tid - 65] = g_acc[r * 128 + tid];
    __syncthreads();
    if (tid < 64) {
        int h = tid;
        float t = asum_s * bv[h];
#pragma unroll 8
        for (int d = 0; d < 64; d++) t += xs_s[d] * Wv[d * 64 + h];
        t += eas[0] * We[h] + eas[1] * We[64 + h] + eas[2] * We[128 + h] + eas[3] * We[192 + h];
        remb_s[h] = t / (asum_s + 1e-16f) + g_rskip[r * 64 + h];
    }
    __syncthreads();
    {
        float acc = g_cvec[tid];
#pragma unroll 8
        for (int h = 0; h < 64; h++) acc += remb_s[h] * W1[(64 + h) * 128 + tid];
        g_Rch[r * 128 + tid] = __float2half(acc);
    }
    if (tid < 64) {
        float acc = 0.f;
#pragma unroll 8
        for (int h = 0; h < 64; h++) acc += Wp[tid * 64 + h] * remb_s[h];
        g_Wpreh[r * 64 + tid] = __float2half(acc);
    }
    if (tid == 0) {
        float acc = 0.f;
        for (int h = 0; h < 64; h++) acc += bp[h] * remb_s[h];
        g_c2[r] = acc;
    }
}

// ---------------- launch 6: flat edge scoring ----------------
__global__ void __launch_bounds__(256) k_edge2(
    const float* __restrict__ W2, const float* __restrict__ b2,
    float* __restrict__ out, int E) {
    int tid = threadIdx.x, lane = tid & 31, warp = tid >> 5;
    int g = lane >> 3, j = lane & 7;
    float w216[16];
#pragma unroll
    for (int k = 0; k < 16; k++) w216[k] = __ldg(W2 + 16 * j + k);
    float b2v = __ldg(b2);
    int gwarp = blockIdx.x * 8 + warp;
    int nwarp = gridDim.x * 8;
    for (int base = gwarp * 4; base < E; base += nwarp * 4) {
        int i = base + g;
        bool valid = i < E;
        const Rec* rp = &g_rec[valid ? i : 0];
        int4 hdr = __ldg((const int4*)rp);
        int o = hdr.x, e = hdr.y, r = hdr.z;
        const uint4* Orow = (const uint4*)(g_Oh + (long long)o * 128);
        uint4 O0 = __ldg(Orow + 2 * j);
        uint4 O1 = __ldg(Orow + 2 * j + 1);
        uint4 xq = __ldg((const uint4*)(g_xoh + (long long)o * 64) + j);
        const uint4* Rrow = (const uint4*)(g_Rch + r * 128);
        uint4 R0 = __ldg(Rrow + 2 * j);       // L1-resident: consecutive edges share r
        uint4 R1 = __ldg(Rrow + 2 * j + 1);
        uint4 pq = __ldg((const uint4*)(g_Wpreh + r * 64) + j);
        float part = 0.f;
        {
            const unsigned* Ou = (const unsigned*)&O0;
            const unsigned* Ru = (const unsigned*)&R0;
#pragma unroll
            for (int k = 0; k < 4; k++) {
                float2 of = __half22float2(*(const half2*)&Ou[k]);
                float2 rf = __half22float2(*(const half2*)&Ru[k]);
                part += fmaxf(of.x + rf.x, 0.f) * w216[2 * k]
                      + fmaxf(of.y + rf.y, 0.f) * w216[2 * k + 1];
            }
            const unsigned* Ou1 = (const unsigned*)&O1;
            const unsigned* Ru1 = (const unsigned*)&R1;
#pragma unroll
            for (int k = 0; k < 4; k++) {
                float2 of = __half22float2(*(const half2*)&Ou1[k]);
                float2 rf = __half22float2(*(const half2*)&Ru1[k]);
                part += fmaxf(of.x + rf.x, 0.f) * w216[8 + 2 * k]
                      + fmaxf(of.y + rf.y, 0.f) * w216[8 + 2 * k + 1];
            }
        }
        {
            const unsigned* xu = (const unsigned*)&xq;
            const unsigned* pu = (const unsigned*)&pq;
            float d = 0.f;
#pragma unroll
            for (int k = 0; k < 4; k++) {
                float2 xf = __half22float2(*(const half2*)&xu[k]);
                float2 pf = __half22float2(*(const half2*)&pu[k]);
                d += xf.x * pf.x + xf.y * pf.y;
            }
            part += 0.125f * d;
        }
        part += __shfl_xor_sync(0xffffffffu, part, 1);
        part += __shfl_xor_sync(0xffffffffu, part, 2);
        part += __shfl_xor_sync(0xffffffffu, part, 4);
        if (j == 0 && valid) {
            float v = part + 0.125f * __ldg(g_c2 + r) + b2v;
            out[e] = fminf(fmaxf(v, -10.f), 10.f);
        }
    }
}

// ---------------- launch ----------------
extern "C" void kernel_launch(void* const* d_in, const int* in_sizes, int n_in,
                              void* d_out, int out_size) {
    const float* xo   = (const float*)d_in[0];
    const float* xr   = (const float*)d_in[1];
    const float* eat  = (const float*)d_in[2];
    const int*   oidx = (const int*)d_in[3];
    const int*   ridx = (const int*)d_in[4];
    const float* omg  = (const float*)d_in[5];
    const float* Wk   = (const float*)d_in[6];
    const float* bk   = (const float*)d_in[7];
    const float* Wq   = (const float*)d_in[8];
    const float* bq   = (const float*)d_in[9];
    const float* Wv   = (const float*)d_in[10];
    const float* bv   = (const float*)d_in[11];
    const float* We   = (const float*)d_in[12];
    const float* Wsk  = (const float*)d_in[13];
    const float* bsk  = (const float*)d_in[14];
    const float* Wp   = (const float*)d_in[15];
    const float* bp   = (const float*)d_in[16];
    const float* W1   = (const float*)d_in[17];
    const float* b1   = (const float*)d_in[18];
    const float* W2   = (const float*)d_in[19];
    const float* b2   = (const float*)d_in[20];
    float* out = (float*)d_out;
    int NOv = in_sizes[0] / 64;
    int NRv = in_sizes[1] / 32;
    int E   = in_sizes[3];
    int NOt = (NOv + 63) / 64;

    const int kO_smem = (64 * 68 + 64 * 128) * 4;  // 50176 B
    cudaFuncSetAttribute(k_Oscat, cudaFuncAttributeMaxDynamicSharedMemorySize, kO_smem);

    k_preh<<<NRv + 65 + 256 + 128, 128>>>(xr, Wq, bq, Wk, bk, We, Wsk, bsk,
                                          omg, W1, b1, bp, Wp, ridx, NRv, E);
    k_scan<<<1, 1024>>>(NRv);
    k_Oscat<<<NOt + 512, 256, kO_smem>>>(xo, NOv, NOt, ridx, oidx, eat, E);
    k_att1<<<NRv * 4, 256>>>();
    k_rider<<<NRv, 128>>>(Wv, bv, We, Wp, bp, W1);
    k_edge2<<<2048, 256>>>(W2, b2, out, E);
}

// round 9
// speedup vs baseline: 1.8333x; 1.0001x over previous
#include <cuda_runtime.h>
#include <cuda_fp16.h>

#define NO_MAX 100000
#define NR_MAX 1000
#define E_MAX  1000000

struct __align__(16) Rec { int o; int e; int r; int pad1; float4 ea; };  // 32B

// ---------------- scratch (device globals; no allocations) ----------------
__device__ float g_A[NR_MAX * 64];
__device__ float g_c1[NR_MAX];
__device__ float g_qWe[NR_MAX * 4];
__device__ float g_rskip[NR_MAX * 64];
__device__ float g_Wc[64 * 128];
__device__ float g_cvec[128];
__device__ int   g_cnt_pad[NR_MAX * 32];
__device__ int   g_cursor_pad[NR_MAX * 32];
__device__ int   g_counts[NR_MAX];
__device__ int   g_starts[NR_MAX];
__device__ float g_acc[NR_MAX * 128];
__device__ float g_c2[NR_MAX];
__device__ __align__(16) Rec g_rec[E_MAX];
__device__ __align__(16) __half g_Oh[(long long)NO_MAX * 128];
__device__ __align__(16) __half g_xoh[(long long)NO_MAX * 64];
__device__ __align__(16) __half g_Rch[NR_MAX * 128];
__device__ __align__(16) __half g_Wpreh[NR_MAX * 64];

__device__ __forceinline__ unsigned long long fma2(unsigned long long a,
                                                   unsigned long long b,
                                                   unsigned long long c) {
    unsigned long long d;
    asm("fma.rn.f32x2 %0, %1, %2, %3;" : "=l"(d) : "l"(a), "l"(b), "l"(c));
    return d;
}
__device__ __forceinline__ unsigned long long pack2(float x) {
    unsigned long long d;
    asm("mov.b64 %0, {%1, %1};" : "=l"(d) : "r"(__float_as_uint(x)));
    return d;
}
__device__ __forceinline__ float2 unpack2(unsigned long long v) {
    unsigned lo, hi;
    asm("mov.b64 {%0, %1}, %2;" : "=r"(lo), "=r"(hi) : "l"(v));
    return make_float2(__uint_as_float(lo), __uint_as_float(hi));
}

// ---------------- launch 1: rider precompute + const + Wc + histogram + acc-zero ----------------
__global__ void __launch_bounds__(128) k_preh(
    const float* __restrict__ xr,
    const float* __restrict__ Wq, const float* __restrict__ bq,
    const float* __restrict__ Wk, const float* __restrict__ bk,
    const float* __restrict__ We,
    const float* __restrict__ Wsk, const float* __restrict__ bsk,
    const float* __restrict__ omg, const float* __restrict__ W1,
    const float* __restrict__ b1, const float* __restrict__ bp,
    const float* __restrict__ Wp, const int* __restrict__ ridx,
    int NRv, int E) {
    int b = blockIdx.x, h = threadIdx.x;
    if (b < NRv) {
        int r = b;
        __shared__ float xs[32], qs[64];
        if (h < 32) xs[h] = xr[r * 32 + h];
        __syncthreads();
        if (h < 64) {
            float q = bq[h];
#pragma unroll 8
            for (int d = 0; d < 32; d++) q += xs[d] * Wq[d * 64 + h];
            qs[h] = q;
            float sk = bsk[h];
#pragma unroll 8
            for (int d = 0; d < 32; d++) sk += xs[d] * Wsk[d * 64 + h];
            g_rskip[r * 64 + h] = sk;
        }
        __syncthreads();
        if (h < 64) {
            float a = 0.f;
#pragma unroll 8
            for (int t = 0; t < 64; t++) a += Wk[h * 64 + t] * qs[t];
            g_A[r * 64 + h] = a;
        }
        if (h < 4) {
            float w = 0.f;
            for (int t = 0; t < 64; t++) w += We[h * 64 + t] * qs[t];
            g_qWe[r * 4 + h] = w;
        }
        if (h == 0) {
            float c = 0.f;
            for (int t = 0; t < 64; t++) c += bk[t] * qs[t];
            g_c1[r] = c;
        }
    } else if (b == NRv) {
        float c = b1[h];
        for (int m = 0; m < 32; m++) c += omg[m] * W1[(128 + m) * 128 + h];
        for (int d = 0; d < 64; d++) c += bp[d] * W1[d * 128 + h];
        g_cvec[h] = c;
    } else if (b < NRv + 65) {
        int d = b - NRv - 1;
        __shared__ float wp[64];
        if (h < 64) wp[h] = Wp[d * 64 + h];
        __syncthreads();
        float acc = 0.f;
#pragma unroll 8
        for (int t = 0; t < 64; t++) acc += wp[t] * W1[t * 128 + h];
        g_Wc[d * 128 + h] = acc;
    } else {
        int idx = b - (NRv + 65);
        if (idx < 256) {
            __shared__ int sh[NR_MAX];
            for (int i = h; i < NRv; i += 128) sh[i] = 0;
            __syncthreads();
            for (int e = idx * 128 + h; e < E; e += 256 * 128)
                atomicAdd(&sh[ridx[e]], 1);
            __syncthreads();
            for (int i = h; i < NRv; i += 128) {
                int c = sh[i];
                if (c) atomicAdd(&g_cnt_pad[i * 32], c);
            }
        } else {
            int z = idx - 256;
            int t = z * 128 + h;
            for (int i = t; i < NRv * 128; i += 128 * 128) g_acc[i] = 0.f;
        }
    }
}

// ---------------- launch 2: scan ----------------
__global__ void k_scan(int NRv) {
    __shared__ int s[1024];
    int t = threadIdx.x;
    int v = (t < NRv) ? g_cnt_pad[t * 32] : 0;
    if (t < NRv) g_cnt_pad[t * 32] = 0;
    s[t] = v;
    __syncthreads();
    for (int off = 1; off < 1024; off <<= 1) {
        int u = (t >= off) ? s[t - off] : 0;
        __syncthreads();
        s[t] += u;
        __syncthreads();
    }
    if (t < NRv) {
        int st = s[t] - v;
        g_starts[t] = st;
        g_counts[t] = v;
        g_cursor_pad[t * 32] = st;
    }
}

// ---------------- launch 3: O-GEMM tiles + scatter blocks ----------------
__global__ void __launch_bounds__(256) k_Oscat(
    const float* __restrict__ xo, int NOv, int NOt,
    const int* __restrict__ ridx, const int* __restrict__ oidx,
    const float* __restrict__ eat, int E) {
    int tid = threadIdx.x;
    if ((int)blockIdx.x >= NOt) {
        int b = blockIdx.x - NOt;
        for (int e = b * 256 + tid; e < E; e += 512 * 256) {
            int r = ridx[e];
            int pos = atomicAdd(&g_cursor_pad[r * 32], 1);
            Rec* rp = &g_rec[pos];
            *(int4*)rp = make_int4(oidx[e], e, r, 0);
            rp->ea = ((const float4*)eat)[e];
        }
        return;
    }
    extern __shared__ __align__(16) float dsm[];
    float* Xs  = dsm;            // [64][68]
    float* Wcs = dsm + 64 * 68;  // [64][128]
    int tx = tid & 15, ty = tid >> 4;
    int row0 = blockIdx.x * 64;
    for (int i = tid; i < 64 * 32; i += 256)
        ((float4*)Wcs)[i] = ((const float4*)g_Wc)[i];
    for (int i = tid; i < 64 * 16; i += 256) {
        int row = i >> 4, kq = i & 15;
        float4 xv = make_float4(0.f, 0.f, 0.f, 0.f);
        int gr = row0 + row;
        if (gr < NOv) xv = ((const float4*)xo)[gr * 16 + kq];
        *((float4*)(Xs + row * 68 + kq * 4)) = xv;
    }
    __syncthreads();
    for (int i = tid; i < 64 * 32; i += 256) {
        int row = i >> 5, c = i & 31;
        int gr = row0 + row;
        if (gr < NOv) {
            float a = Xs[row * 68 + 2 * c], b = Xs[row * 68 + 2 * c + 1];
            ((half2*)g_xoh)[(long long)gr * 32 + c] = __floats2half2_rn(a, b);
        }
    }
    unsigned long long acc2[4][4];
#pragma unroll
    for (int i = 0; i < 4; i++)
#pragma unroll
        for (int j = 0; j < 4; j++) acc2[i][j] = 0ull;
#pragma unroll 8
    for (int k = 0; k < 64; k++) {
        unsigned long long ab[4];
#pragma unroll
        for (int i = 0; i < 4; i++) ab[i] = pack2(Xs[(ty * 4 + i) * 68 + k]);
        const float* wrow = Wcs + k * 128;
        unsigned long long b0 = *(const unsigned long long*)(wrow + tx * 4);
        unsigned long long b1 = *(const unsigned long long*)(wrow + tx * 4 + 2);
        unsigned long long b2 = *(const unsigned long long*)(wrow + 64 + tx * 4);
        unsigned long long b3 = *(const unsigned long long*)(wrow + 64 + tx * 4 + 2);
#pragma unroll
        for (int i = 0; i < 4; i++) {
            acc2[i][0] = fma2(ab[i], b0, acc2[i][0]);
            acc2[i][1] = fma2(ab[i], b1, acc2[i][1]);
            acc2[i][2] = fma2(ab[i], b2, acc2[i][2]);
            acc2[i][3] = fma2(ab[i], b3, acc2[i][3]);
        }
    }
#pragma unroll
    for (int i = 0; i < 4; i++) {
        int gr = row0 + ty * 4 + i;
        if (gr < NOv) {
            half2* dst = (half2*)g_Oh + (long long)gr * 64;
            float2 p0 = unpack2(acc2[i][0]);
            float2 p1 = unpack2(acc2[i][1]);
            float2 p2 = unpack2(acc2[i][2]);
            float2 p3 = unpack2(acc2[i][3]);
            dst[tx * 2]          = __floats2half2_rn(p0.x, p0.y);
            dst[tx * 2 + 1]      = __floats2half2_rn(p1.x, p1.y);
            dst[32 + tx * 2]     = __floats2half2_rn(p2.x, p2.y);
            dst[32 + tx * 2 + 1] = __floats2half2_rn(p3.x, p3.y);
        }
    }
}

// ---------------- launch 4: attention partials (4 CTAs/rider, unroll x2) ----------------
__global__ void __launch_bounds__(256) k_att1() {
    int bid = blockIdx.x;
    int r = bid >> 2, chunk = bid & 3;
    int tid = threadIdx.x, lane = tid & 31, warp = tid >> 5;
    int g = lane >> 3, j = lane & 7;
    __shared__ __align__(16) float wsum[8][64];
    __shared__ __align__(16) float wsc[8][8];
    float a8[8];
#pragma unroll
    for (int k = 0; k < 8; k++) a8[k] = __ldg(g_A + r * 64 + 8 * j + k);
    float q0 = __ldg(g_qWe + r * 4), q1 = __ldg(g_qWe + r * 4 + 1);
    float q2 = __ldg(g_qWe + r * 4 + 2), q3 = __ldg(g_qWe + r * 4 + 3);
    float c1 = __ldg(g_c1 + r);
    int start = g_starts[r], cnt = g_counts[r];

    float xs8[8];
#pragma unroll
    for (int k = 0; k < 8; k++) xs8[k] = 0.f;
    float asum = 0.f, e0 = 0.f, e1 = 0.f, e2 = 0.f, e3 = 0.f;
    // unroll x2: edges (base+g) and (base+128+g) per iteration -> 2 hdr + 2 x loads in flight
    for (int base = (chunk * 8 + warp) * 4; base < cnt; base += 256) {
        int iA = base + g, iB = base + 128 + g;
        bool vA = iA < cnt, vB = iB < cnt;
        const Rec* rpA = &g_rec[start + (vA ? iA : 0)];
        const Rec* rpB = &g_rec[start + (vB ? iB : 0)];
        int oA = __ldg(&rpA->o);
        int oB = __ldg(&rpB->o);
        float4 eaA = __ldg(&rpA->ea);
        float4 eaB = __ldg(&rpB->ea);
        uint4 xqA = __ldg((const uint4*)(g_xoh + (long long)oA * 64) + j);
        uint4 xqB = __ldg((const uint4*)(g_xoh + (long long)oB * 64) + j);
        // A
        float2 xA0 = __half22float2(*(const half2*)&xqA.x);
        float2 xA1 = __half22float2(*(const half2*)&xqA.y);
        float2 xA2 = __half22float2(*(const half2*)&xqA.z);
        float2 xA3 = __half22float2(*(const half2*)&xqA.w);
        float pdA = xA0.x * a8[0] + xA0.y * a8[1] + xA1.x * a8[2] + xA1.y * a8[3]
                  + xA2.x * a8[4] + xA2.y * a8[5] + xA3.x * a8[6] + xA3.y * a8[7];
        // B
        float2 xB0 = __half22float2(*(const half2*)&xqB.x);
        float2 xB1 = __half22float2(*(const half2*)&xqB.y);
        float2 xB2 = __half22float2(*(const half2*)&xqB.z);
        float2 xB3 = __half22float2(*(const half2*)&xqB.w);
        float pdB = xB0.x * a8[0] + xB0.y * a8[1] + xB1.x * a8[2] + xB1.y * a8[3]
                  + xB2.x * a8[4] + xB2.y * a8[5] + xB3.x * a8[6] + xB3.y * a8[7];
        // interleaved independent shfl chains
        pdA += __shfl_xor_sync(0xffffffffu, pdA, 1);
        pdB += __shfl_xor_sync(0xffffffffu, pdB, 1);
        pdA += __shfl_xor_sync(0xffffffffu, pdA, 2);
        pdB += __shfl_xor_sync(0xffffffffu, pdB, 2);
        pdA += __shfl_xor_sync(0xffffffffu, pdA, 4);
        pdB += __shfl_xor_sync(0xffffffffu, pdB, 4);
        float dotA = pdA + c1 + eaA.x * q0 + eaA.y * q1 + eaA.z * q2 + eaA.w * q3;
        float dotB = pdB + c1 + eaB.x * q0 + eaB.y * q1 + eaB.z * q2 + eaB.w * q3;
        float wA = vA ? __expf(0.125f * dotA) : 0.f;  // shift-invariant softmax
        float wB = vB ? __expf(0.125f * dotB) : 0.f;
        asum += wA + wB;
        e0 += wA * eaA.x + wB * eaB.x;
        e1 += wA * eaA.y + wB * eaB.y;
        e2 += wA * eaA.z + wB * eaB.z;
        e3 += wA * eaA.w + wB * eaB.w;
        xs8[0] += wA * xA0.x + wB * xB0.x; xs8[1] += wA * xA0.y + wB * xB0.y;
        xs8[2] += wA * xA1.x + wB * xB1.x; xs8[3] += wA * xA1.y + wB * xB1.y;
        xs8[4] += wA * xA2.x + wB * xB2.x; xs8[5] += wA * xA2.y + wB * xB2.y;
        xs8[6] += wA * xA3.x + wB * xB3.x; xs8[7] += wA * xA3.y + wB * xB3.y;
    }
#pragma unroll
    for (int k = 0; k < 8; k++) {
        float v = xs8[k];
        v += __shfl_xor_sync(0xffffffffu, v, 8);
        v += __shfl_xor_sync(0xffffffffu, v, 16);
        xs8[k] = v;
    }
    if (lane < 8) {
#pragma unroll
        for (int k = 0; k < 8; k++) wsum[warp][lane * 8 + k] = xs8[k];
    }
    float sc[5] = {asum, e0, e1, e2, e3};
#pragma unroll
    for (int m = 0; m < 5; m++) {
        float v = sc[m];
        v += __shfl_xor_sync(0xffffffffu, v, 16);
        v += __shfl_xor_sync(0xffffffffu, v, 8);
        v += __shfl_xor_sync(0xffffffffu, v, 4);
        v += __shfl_xor_sync(0xffffffffu, v, 2);
        v += __shfl_xor_sync(0xffffffffu, v, 1);
        sc[m] = v * 0.125f;  // each edge counted by 8 lanes
    }
    if (lane == 0) {
#pragma unroll
        for (int m = 0; m < 5; m++) wsc[warp][m] = sc[m];
    }
    __syncthreads();
    if (tid < 64) {
        float v = 0.f;
#pragma unroll
        for (int w = 0; w < 8; w++) v += wsum[w][tid];
        atomicAdd(&g_acc[r * 128 + tid], v);
    }
    if (tid >= 64 && tid < 69) {
        int m = tid - 64;
        float v = 0.f;
#pragma unroll
        for (int w = 0; w < 8; w++) v += wsc[w][m];
        atomicAdd(&g_acc[r * 128 + 64 + m], v);
    }
}

// ---------------- launch 5: per-rider finish ----------------
__global__ void __launch_bounds__(128) k_rider(
    const float* __restrict__ Wv, const float* __restrict__ bv,
    const float* __restrict__ We, const float* __restrict__ Wp,
    const float* __restrict__ bp, const float* __restrict__ W1) {
    int r = blockIdx.x, tid = threadIdx.x;
    __shared__ __align__(16) float xs_s[64];
    __shared__ __align__(16) float remb_s[64];
    __shared__ __align__(16) float eas[4];
    __shared__ float asum_s;
    if (tid < 64) xs_s[tid] = g_acc[r * 128 + tid];
    if (tid == 64) asum_s = g_acc[r * 128 + 64];
    if (tid > 64 && tid < 69) eas[tid - 65] = g_acc[r * 128 + tid];
    __syncthreads();
    if (tid < 64) {
        int h = tid;
        float t = asum_s * bv[h];
#pragma unroll 8
        for (int d = 0; d < 64; d++) t += xs_s[d] * Wv[d * 64 + h];
        t += eas[0] * We[h] + eas[1] * We[64 + h] + eas[2] * We[128 + h] + eas[3] * We[192 + h];
        remb_s[h] = t / (asum_s + 1e-16f) + g_rskip[r * 64 + h];
    }
    __syncthreads();
    {
        float acc = g_cvec[tid];
#pragma unroll 8
        for (int h = 0; h < 64; h++) acc += remb_s[h] * W1[(64 + h) * 128 + tid];
        g_Rch[r * 128 + tid] = __float2half(acc);
    }
    if (tid < 64) {
        float acc = 0.f;
#pragma unroll 8
        for (int h = 0; h < 64; h++) acc += Wp[tid * 64 + h] * remb_s[h];
        g_Wpreh[r * 64 + tid] = __float2half(acc);
    }
    if (tid == 0) {
        float acc = 0.f;
        for (int h = 0; h < 64; h++) acc += bp[h] * remb_s[h];
        g_c2[r] = acc;
    }
}

// ---------------- launch 6: flat edge scoring (unroll x2) ----------------
__global__ void __launch_bounds__(256) k_edge2(
    const float* __restrict__ W2, const float* __restrict__ b2,
    float* __restrict__ out, int E) {
    int tid = threadIdx.x, lane = tid & 31, warp = tid >> 5;
    int g = lane >> 3, j = lane & 7;
    float w216[16];
#pragma unroll
    for (int k = 0; k < 16; k++) w216[k] = __ldg(W2 + 16 * j + k);
    float b2v = __ldg(b2);
    int gwarp = blockIdx.x * 8 + warp;
    int nwarp = gridDim.x * 8;
    // each warp covers 8 consecutive edges per iteration: base+g and base+4+g
    for (int base = gwarp * 8; base < E; base += nwarp * 8) {
        int iA = base + g, iB = base + 4 + g;
        bool vA = iA < E, vB = iB < E;
        const Rec* rpA = &g_rec[vA ? iA : 0];
        const Rec* rpB = &g_rec[vB ? iB : 0];
        int4 hdrA = __ldg((const int4*)rpA);
        int4 hdrB = __ldg((const int4*)rpB);
        int oA = hdrA.x, eA = hdrA.y, rA = hdrA.z;
        int oB = hdrB.x, eB = hdrB.y, rB = hdrB.z;
        const uint4* OrowA = (const uint4*)(g_Oh + (long long)oA * 128);
        const uint4* OrowB = (const uint4*)(g_Oh + (long long)oB * 128);
        uint4 OA0 = __ldg(OrowA + 2 * j);
        uint4 OB0 = __ldg(OrowB + 2 * j);
        uint4 OA1 = __ldg(OrowA + 2 * j + 1);
        uint4 OB1 = __ldg(OrowB + 2 * j + 1);
        uint4 xqA = __ldg((const uint4*)(g_xoh + (long long)oA * 64) + j);
        uint4 xqB = __ldg((const uint4*)(g_xoh + (long long)oB * 64) + j);
        uint4 RA0 = __ldg((const uint4*)(g_Rch + rA * 128) + 2 * j);
        uint4 RB0 = __ldg((const uint4*)(g_Rch + rB * 128) + 2 * j);
        uint4 RA1 = __ldg((const uint4*)(g_Rch + rA * 128) + 2 * j + 1);
        uint4 RB1 = __ldg((const uint4*)(g_Rch + rB * 128) + 2 * j + 1);
        uint4 pqA = __ldg((const uint4*)(g_Wpreh + rA * 64) + j);
        uint4 pqB = __ldg((const uint4*)(g_Wpreh + rB * 64) + j);
        float partA = 0.f, partB = 0.f;
        {
            const unsigned* Ou = (const unsigned*)&OA0;
            const unsigned* Ru = (const unsigned*)&RA0;
            const unsigned* Ov = (const unsigned*)&OB0;
            const unsigned* Rv = (const unsigned*)&RB0;
#pragma unroll
            for (int k = 0; k < 4; k++) {
                float2 of = __half22float2(*(const half2*)&Ou[k]);
                float2 rf = __half22float2(*(const half2*)&Ru[k]);
                partA += fmaxf(of.x + rf.x, 0.f) * w216[2 * k]
                       + fmaxf(of.y + rf.y, 0.f) * w216[2 * k + 1];
                float2 og = __half22float2(*(const half2*)&Ov[k]);
                float2 rg = __half22float2(*(const half2*)&Rv[k]);
                partB += fmaxf(og.x + rg.x, 0.f) * w216[2 * k]
                       + fmaxf(og.y + rg.y, 0.f) * w216[2 * k + 1];
            }
            const unsigned* Ou1 = (const unsigned*)&OA1;
            const unsigned* Ru1 = (const unsigned*)&RA1;
            const unsigned* Ov1 = (const unsigned*)&OB1;
            const unsigned* Rv1 = (const unsigned*)&RB1;
#pragma unroll
            for (int k = 0; k < 4; k++) {
                float2 of = __half22float2(*(const half2*)&Ou1[k]);
                float2 rf = __half22float2(*(const half2*)&Ru1[k]);
                partA += fmaxf(of.x + rf.x, 0.f) * w216[8 + 2 * k]
                       + fmaxf(of.y + rf.y, 0.f) * w216[8 + 2 * k + 1];
                float2 og = __half22float2(*(const half2*)&Ov1[k]);
                float2 rg = __half22float2(*(const half2*)&Rv1[k]);
                partB += fmaxf(og.x + rg.x, 0.f) * w216[8 + 2 * k]
                       + fmaxf(og.y + rg.y, 0.f) * w216[8 + 2 * k + 1];
            }
        }
        {
            const unsigned* xu = (const unsigned*)&xqA;
            const unsigned* pu = (const unsigned*)&pqA;
            const unsigned* xv = (const unsigned*)&xqB;
            const unsigned* pv = (const unsigned*)&pqB;
            float dA = 0.f, dB = 0.f;
#pragma unroll
            for (int k = 0; k < 4; k++) {
                float2 xf = __half22float2(*(const half2*)&xu[k]);
                float2 pf = __half22float2(*(const half2*)&pu[k]);
                dA += xf.x * pf.x + xf.y * pf.y;
                float2 xg = __half22float2(*(const half2*)&xv[k]);
                float2 pg = __half22float2(*(const half2*)&pv[k]);
                dB += xg.x * pg.x + xg.y * pg.y;
            }
            partA += 0.125f * dA;
            partB += 0.125f * dB;
        }
        partA += __shfl_xor_sync(0xffffffffu, partA, 1);
        partB += __shfl_xor_sync(0xffffffffu, partB, 1);
        partA += __shfl_xor_sync(0xffffffffu, partA, 2);
        partB += __shfl_xor_sync(0xffffffffu, partB, 2);
        partA += __shfl_xor_sync(0xffffffffu, partA, 4);
        partB += __shfl_xor_sync(0xffffffffu, partB, 4);
        if (j == 0) {
            if (vA) {
                float v = partA + 0.125f * __ldg(g_c2 + rA) + b2v;
                out[eA] = fminf(fmaxf(v, -10.f), 10.f);
            }
            if (vB) {
                float v = partB + 0.125f * __ldg(g_c2 + rB) + b2v;
                out[eB] = fminf(fmaxf(v, -10.f), 10.f);
            }
        }
    }
}

// ---------------- launch ----------------
extern "C" void kernel_launch(void* const* d_in, const int* in_sizes, int n_in,
                              void* d_out, int out_size) {
    const float* xo   = (const float*)d_in[0];
    const float* xr   = (const float*)d_in[1];
    const float* eat  = (const float*)d_in[2];
    const int*   oidx = (const int*)d_in[3];
    const int*   ridx = (const int*)d_in[4];
    const float* omg  = (const float*)d_in[5];
    const float* Wk   = (const float*)d_in[6];
    const float* bk   = (const float*)d_in[7];
    const float* Wq   = (const float*)d_in[8];
    const float* bq   = (const float*)d_in[9];
    const float* Wv   = (const float*)d_in[10];
    const float* bv   = (const float*)d_in[11];
    const float* We   = (const float*)d_in[12];
    const float* Wsk  = (const float*)d_in[13];
    const float* bsk  = (const float*)d_in[14];
    const float* Wp   = (const float*)d_in[15];
    const float* bp   = (const float*)d_in[16];
    const float* W1   = (const float*)d_in[17];
    const float* b1   = (const float*)d_in[18];
    const float* W2   = (const float*)d_in[19];
    const float* b2   = (const float*)d_in[20];
    float* out = (float*)d_out;
    int NOv = in_sizes[0] / 64;
    int NRv = in_sizes[1] / 32;
    int E   = in_sizes[3];
    int NOt = (NOv + 63) / 64;

    const int kO_smem = (64 * 68 + 64 * 128) * 4;  // 50176 B
    cudaFuncSetAttribute(k_Oscat, cudaFuncAttributeMaxDynamicSharedMemorySize, kO_smem);

    k_preh<<<NRv + 65 + 256 + 128, 128>>>(xr, Wq, bq, Wk, bk, We, Wsk, bsk,
                                          omg, W1, b1, bp, Wp, ridx, NRv, E);
    k_scan<<<1, 1024>>>(NRv);
    k_Oscat<<<NOt + 512, 256, kO_smem>>>(xo, NOv, NOt, ridx, oidx, eat, E);
    k_att1<<<NRv * 4, 256>>>();
    k_rider<<<NRv, 128>>>(Wv, bv, We, Wp, bp, W1);
    k_edge2<<<2048, 256>>>(W2, b2, out, E);
}